// round 1
// baseline (speedup 1.0000x reference)
#include <cuda_runtime.h>
#include <math.h>

// ---------------------------------------------------------------------------
// AdaLoRAWithBase: out = x + x @ (base + x_a x_b^T)
// Restructured:   out = x + x@base + sum_r t[b,r] * x_b[b,:,r]
//                 t[b,r] = sum_c x[b,c] * x_a[b,c,r]
// where [x_a | x_b] = GELU(LN(ada) @ W1 + b1) @ W2 + b2
// ---------------------------------------------------------------------------

namespace {
constexpr int Bsz = 256;
constexpr int Dd  = 1024;
constexpr int Aa  = 1024;
constexpr int Ii  = 1024;
constexpr int Rr  = 8;
constexpr int W2N = Dd * Rr * 2;   // 16384
}

// Scratch (device globals; no allocation allowed in kernel_launch)
__device__ __align__(16) float g_cond[Bsz * Aa];                 // 1 MB
__device__ __align__(16) float g_h[Bsz * Ii];                    // 1 MB
__device__ __align__(16) float g_w[(size_t)Bsz * W2N];           // 16 MB
__device__ __align__(16) float g_t[Bsz * Rr];                    // 8 KB

// ---------------------------------------------------------------------------
// LayerNorm over ada_dim (one block per row)
// ---------------------------------------------------------------------------
__global__ void __launch_bounds__(256) ln_kernel(
    const float* __restrict__ ada,
    const float* __restrict__ gamma,
    const float* __restrict__ beta)
{
    int b = blockIdx.x;
    const float* row = ada + (size_t)b * Aa;

    float s = 0.f, s2 = 0.f;
    for (int i = threadIdx.x; i < Aa; i += blockDim.x) {
        float v = row[i];
        s += v; s2 += v * v;
    }
    // warp reduce
    #pragma unroll
    for (int o = 16; o; o >>= 1) {
        s  += __shfl_down_sync(0xFFFFFFFFu, s,  o);
        s2 += __shfl_down_sync(0xFFFFFFFFu, s2, o);
    }
    __shared__ float red0[8], red1[8];
    __shared__ float mv[2];
    int wid = threadIdx.x >> 5, lid = threadIdx.x & 31;
    if (lid == 0) { red0[wid] = s; red1[wid] = s2; }
    __syncthreads();
    if (threadIdx.x == 0) {
        float ts = 0.f, ts2 = 0.f;
        #pragma unroll
        for (int i = 0; i < 8; i++) { ts += red0[i]; ts2 += red1[i]; }
        float mu  = ts * (1.f / Aa);
        float var = ts2 * (1.f / Aa) - mu * mu;
        mv[0] = mu;
        mv[1] = rsqrtf(var + 1e-5f);
    }
    __syncthreads();
    float mu = mv[0], rs = mv[1];
    for (int i = threadIdx.x; i < Aa; i += blockDim.x) {
        g_cond[(size_t)b * Aa + i] = (row[i] - mu) * rs * gamma[i] + beta[i];
    }
}

// ---------------------------------------------------------------------------
// Tiled fp32 SGEMM: C[M,N] = A[M,K] @ Bm[K,N] (+ epilogue by MODE)
//   MODE 0: C = GELU(acc + bias)       (exact erf GELU)
//   MODE 1: C = acc + bias
//   MODE 2: C = acc + xres + sum_r g_t[m,r] * g_w[m, D*R + n*R + r]
// BM=BN=64, BK=16, 256 threads, 4x4 per thread.
// ---------------------------------------------------------------------------
template <int MODE>
__global__ void __launch_bounds__(256) sgemm_kernel(
    const float* __restrict__ A,
    const float* __restrict__ Bm,
    const float* __restrict__ bias,
    float* __restrict__ C,
    int N, int K,
    const float* __restrict__ xres)
{
    constexpr int BM = 64, BN = 64, BK = 16;
    __shared__ float As[BK][BM];     // transposed A tile
    __shared__ float Bs[BK][BN];

    int tid = threadIdx.x;
    int tx = tid & 15;               // 0..15 -> 4 cols each
    int ty = tid >> 4;               // 0..15 -> 4 rows each
    int n0 = blockIdx.x * BN;
    int m0 = blockIdx.y * BM;

    // load indices
    int ar = tid >> 2;               // 0..63  (row within A tile)
    int ac = (tid & 3) << 2;         // 0,4,8,12 (col within A tile)
    int br = tid >> 4;               // 0..15  (row within B tile)
    int bc = (tid & 15) << 2;        // 0..60  (col within B tile)

    float acc[4][4] = {};

    for (int k0 = 0; k0 < K; k0 += BK) {
        float4 av = *reinterpret_cast<const float4*>(
            A + (size_t)(m0 + ar) * K + k0 + ac);
        As[ac + 0][ar] = av.x;
        As[ac + 1][ar] = av.y;
        As[ac + 2][ar] = av.z;
        As[ac + 3][ar] = av.w;

        float4 bv = *reinterpret_cast<const float4*>(
            Bm + (size_t)(k0 + br) * N + n0 + bc);
        *reinterpret_cast<float4*>(&Bs[br][bc]) = bv;

        __syncthreads();

        #pragma unroll
        for (int k = 0; k < BK; k++) {
            float a[4], bb[4];
            #pragma unroll
            for (int i = 0; i < 4; i++) a[i]  = As[k][ty * 4 + i];
            #pragma unroll
            for (int j = 0; j < 4; j++) bb[j] = Bs[k][tx * 4 + j];
            #pragma unroll
            for (int i = 0; i < 4; i++)
                #pragma unroll
                for (int j = 0; j < 4; j++)
                    acc[i][j] += a[i] * bb[j];
        }
        __syncthreads();
    }

    // epilogue
    #pragma unroll
    for (int i = 0; i < 4; i++) {
        int m = m0 + ty * 4 + i;
        if (MODE == 2) {
            // per-row rank-8 coefficients
            float tr[Rr];
            #pragma unroll
            for (int r = 0; r < Rr; r++) tr[r] = g_t[(size_t)m * Rr + r];
            const float* wb_row = g_w + (size_t)m * W2N + (size_t)Dd * Rr;
            #pragma unroll
            for (int j = 0; j < 4; j++) {
                int n = n0 + tx * 4 + j;
                float4 w0 = *reinterpret_cast<const float4*>(wb_row + (size_t)n * Rr);
                float4 w1 = *reinterpret_cast<const float4*>(wb_row + (size_t)n * Rr + 4);
                float lr = tr[0] * w0.x + tr[1] * w0.y + tr[2] * w0.z + tr[3] * w0.w
                         + tr[4] * w1.x + tr[5] * w1.y + tr[6] * w1.z + tr[7] * w1.w;
                C[(size_t)m * N + n] = acc[i][j] + xres[(size_t)m * N + n] + lr;
            }
        } else {
            #pragma unroll
            for (int j = 0; j < 4; j++) {
                int n = n0 + tx * 4 + j;
                float v = acc[i][j] + bias[n];
                if (MODE == 0) {
                    // exact GELU: 0.5*v*(1+erf(v/sqrt(2)))
                    v = 0.5f * v * (1.f + erff(v * 0.70710678118654752f));
                }
                C[(size_t)m * N + n] = v;
            }
        }
    }
}

// ---------------------------------------------------------------------------
// t[b,r] = sum_d x[b,d] * x_a[b,d,r],  x_a[b,d,r] = g_w[b, d*R + r]
// One block per batch row.
// ---------------------------------------------------------------------------
__global__ void __launch_bounds__(256) t_kernel(const float* __restrict__ x)
{
    int b = blockIdx.x;
    const float* wrow = g_w + (size_t)b * W2N;
    const float* xrow = x + (size_t)b * Dd;

    float acc[Rr] = {};
    for (int d = threadIdx.x; d < Dd; d += blockDim.x) {
        float xv = xrow[d];
        float4 w0 = *reinterpret_cast<const float4*>(wrow + (size_t)d * Rr);
        float4 w1 = *reinterpret_cast<const float4*>(wrow + (size_t)d * Rr + 4);
        acc[0] += xv * w0.x; acc[1] += xv * w0.y;
        acc[2] += xv * w0.z; acc[3] += xv * w0.w;
        acc[4] += xv * w1.x; acc[5] += xv * w1.y;
        acc[6] += xv * w1.z; acc[7] += xv * w1.w;
    }
    // warp reduce all 8
    #pragma unroll
    for (int o = 16; o; o >>= 1)
        #pragma unroll
        for (int r = 0; r < Rr; r++)
            acc[r] += __shfl_down_sync(0xFFFFFFFFu, acc[r], o);

    __shared__ float red[Rr][8];
    int wid = threadIdx.x >> 5, lid = threadIdx.x & 31;
    if (lid == 0) {
        #pragma unroll
        for (int r = 0; r < Rr; r++) red[r][wid] = acc[r];
    }
    __syncthreads();
    if (threadIdx.x < Rr) {
        int r = threadIdx.x;
        float s = 0.f;
        #pragma unroll
        for (int w = 0; w < 8; w++) s += red[r][w];
        g_t[(size_t)b * Rr + r] = s;
    }
}

// ---------------------------------------------------------------------------
extern "C" void kernel_launch(void* const* d_in, const int* in_sizes, int n_in,
                              void* d_out, int out_size)
{
    const float* x    = (const float*)d_in[0];
    const float* ada  = (const float*)d_in[1];
    const float* base = (const float*)d_in[2];
    const float* gam  = (const float*)d_in[3];
    const float* bet  = (const float*)d_in[4];
    const float* W1   = (const float*)d_in[5];
    const float* b1   = (const float*)d_in[6];
    const float* W2   = (const float*)d_in[7];
    const float* b2   = (const float*)d_in[8];
    float* out = (float*)d_out;

    float *cond_p, *h_p, *w_p;
    cudaGetSymbolAddress((void**)&cond_p, g_cond);
    cudaGetSymbolAddress((void**)&h_p, g_h);
    cudaGetSymbolAddress((void**)&w_p, g_w);

    // 1. LayerNorm
    ln_kernel<<<Bsz, 256>>>(ada, gam, bet);

    // 2. h = GELU(cond @ W1 + b1)        [256 x 1024]
    sgemm_kernel<0><<<dim3(Ii / 64, Bsz / 64), 256>>>(cond_p, W1, b1, h_p, Ii, Aa, nullptr);

    // 3. w = h @ W2 + b2                 [256 x 16384]
    sgemm_kernel<1><<<dim3(W2N / 64, Bsz / 64), 256>>>(h_p, W2, b2, w_p, W2N, Ii, nullptr);

    // 4. t[b,r] = sum_d x[b,d]*x_a[b,d,r]
    t_kernel<<<Bsz, 256>>>(x);

    // 5. out = x + x@base + sum_r t*x_b
    sgemm_kernel<2><<<dim3(Dd / 64, Bsz / 64), 256>>>(x, base, nullptr, out, Dd, Aa, x);
}

// round 3
// speedup vs baseline: 1.5329x; 1.5329x over previous
#include <cuda_runtime.h>
#include <cuda_bf16.h>
#include <math.h>
#include <cstdint>

// ---------------------------------------------------------------------------
// AdaLoRAWithBase restructured:
//   out = x + x@base + sum_r t[b,r] * x_b[b,:,r],  t[b,r] = sum_c x[b,c]*x_a[b,c,r]
//   [x_a|x_b] = GELU(LN(ada)@W1+b1) @ W2 + b2
// GEMM2 (dominant, 256x16384x1024) on mma.sync bf16 (HMMA) with hi/lo 3-pass
// split for fp32-grade accuracy. tcgen05 unavailable (compute_103 PTX target).
// ---------------------------------------------------------------------------

namespace {
constexpr int Bsz = 256;
constexpr int Dd  = 1024;
constexpr int Aa  = 1024;
constexpr int Ii  = 1024;
constexpr int Rr  = 8;
constexpr int W2N = Dd * Rr * 2;     // 16384
constexpr int Kd  = Ii;              // 1024

// GEMM2 mma tiling
constexpr int BM = 128, BN = 128, BK = 32;
constexpr int NKT = Kd / BK;         // 32 k-iterations

// smem stage layout (bf16 elems): A rows padded to 40 (80B), B rows to 136 (272B)
constexpr int A_ROWLEN = 40;
constexpr int B_ROWLEN = 136;
constexpr int OFF_AHI = 0;
constexpr int OFF_ALO = BM * A_ROWLEN * 2;            // 10240
constexpr int OFF_BHI = 2 * BM * A_ROWLEN * 2;        // 20480
constexpr int OFF_BLO = OFF_BHI + BK * B_ROWLEN * 2;  // 29184
constexpr int STAGE_BYTES = OFF_BLO + BK * B_ROWLEN * 2;  // 37888
constexpr int SMEM_TOTAL = 2 * STAGE_BYTES;               // 75776
}

// Scratch (device globals)
__device__ __align__(16) float g_cond[Bsz * Aa];
__device__ __align__(16) float g_h[Bsz * Ii];
__device__ __align__(16) float g_w[(size_t)Bsz * W2N];            // 16 MB
__device__ __align__(16) float g_t[Bsz * Rr];
__device__ __align__(16) __nv_bfloat16 g_Ahi[Bsz * Kd];
__device__ __align__(16) __nv_bfloat16 g_Alo[Bsz * Kd];
__device__ __align__(16) __nv_bfloat16 g_Whi[(size_t)Kd * W2N];   // 32 MB [K,N]
__device__ __align__(16) __nv_bfloat16 g_Wlo[(size_t)Kd * W2N];   // 32 MB [K,N]

// ---------------------------------------------------------------------------
// PTX helpers (all baseline sm_80+ features; no 'a'-suffix ISA)
// ---------------------------------------------------------------------------
__device__ __forceinline__ uint32_t smem_u32(const void* p) {
    uint32_t a;
    asm("{ .reg .u64 t; cvta.to.shared.u64 t, %1; cvt.u32.u64 %0, t; }" : "=r"(a) : "l"(p));
    return a;
}
__device__ __forceinline__ void cp_async16(uint32_t saddr, const void* gaddr) {
    asm volatile("cp.async.cg.shared.global [%0], [%1], 16;" :: "r"(saddr), "l"(gaddr) : "memory");
}
__device__ __forceinline__ void cp_commit() {
    asm volatile("cp.async.commit_group;" ::: "memory");
}
template <int N>
__device__ __forceinline__ void cp_wait() {
    asm volatile("cp.async.wait_group %0;" :: "n"(N) : "memory");
}
__device__ __forceinline__ void ldsm_x4(uint32_t& r0, uint32_t& r1, uint32_t& r2, uint32_t& r3,
                                        uint32_t addr) {
    asm volatile("ldmatrix.sync.aligned.m8n8.x4.shared.b16 {%0,%1,%2,%3}, [%4];"
                 : "=r"(r0), "=r"(r1), "=r"(r2), "=r"(r3) : "r"(addr));
}
__device__ __forceinline__ void ldsm_x2_trans(uint32_t& r0, uint32_t& r1, uint32_t addr) {
    asm volatile("ldmatrix.sync.aligned.m8n8.x2.trans.shared.b16 {%0,%1}, [%2];"
                 : "=r"(r0), "=r"(r1) : "r"(addr));
}
__device__ __forceinline__ void mma16816(float* c, uint32_t a0, uint32_t a1, uint32_t a2,
                                         uint32_t a3, uint32_t b0, uint32_t b1) {
    asm volatile(
        "mma.sync.aligned.m16n8k16.row.col.f32.bf16.bf16.f32 "
        "{%0,%1,%2,%3},{%4,%5,%6,%7},{%8,%9},{%0,%1,%2,%3};"
        : "+f"(c[0]), "+f"(c[1]), "+f"(c[2]), "+f"(c[3])
        : "r"(a0), "r"(a1), "r"(a2), "r"(a3), "r"(b0), "r"(b1));
}

// ---------------------------------------------------------------------------
// LayerNorm
// ---------------------------------------------------------------------------
__global__ void __launch_bounds__(256) ln_kernel(
    const float* __restrict__ ada, const float* __restrict__ gamma,
    const float* __restrict__ beta)
{
    int b = blockIdx.x;
    const float* row = ada + (size_t)b * Aa;
    float s = 0.f, s2 = 0.f;
    for (int i = threadIdx.x; i < Aa; i += blockDim.x) {
        float v = row[i]; s += v; s2 += v * v;
    }
    #pragma unroll
    for (int o = 16; o; o >>= 1) {
        s  += __shfl_down_sync(0xFFFFFFFFu, s,  o);
        s2 += __shfl_down_sync(0xFFFFFFFFu, s2, o);
    }
    __shared__ float red0[8], red1[8], mv[2];
    int wid = threadIdx.x >> 5, lid = threadIdx.x & 31;
    if (lid == 0) { red0[wid] = s; red1[wid] = s2; }
    __syncthreads();
    if (threadIdx.x == 0) {
        float ts = 0.f, ts2 = 0.f;
        #pragma unroll
        for (int i = 0; i < 8; i++) { ts += red0[i]; ts2 += red1[i]; }
        float mu = ts * (1.f / Aa);
        float var = ts2 * (1.f / Aa) - mu * mu;
        mv[0] = mu; mv[1] = rsqrtf(var + 1e-5f);
    }
    __syncthreads();
    float mu = mv[0], rs = mv[1];
    for (int i = threadIdx.x; i < Aa; i += blockDim.x)
        g_cond[(size_t)b * Aa + i] = (row[i] - mu) * rs * gamma[i] + beta[i];
}

// ---------------------------------------------------------------------------
// fp32 SGEMM for GEMM1 (MODE 0: GELU) and GEMM3 (MODE 2: residual + rank-8)
// ---------------------------------------------------------------------------
template <int MODE>
__global__ void __launch_bounds__(256) sgemm_kernel(
    const float* __restrict__ A, const float* __restrict__ Bm,
    const float* __restrict__ bias, float* __restrict__ C,
    int N, int K, const float* __restrict__ xres)
{
    constexpr int TBM = 64, TBN = 64, TBK = 16;
    __shared__ float As[TBK][TBM];
    __shared__ float Bs[TBK][TBN];
    int tid = threadIdx.x;
    int tx = tid & 15, ty = tid >> 4;
    int n0 = blockIdx.x * TBN, m0 = blockIdx.y * TBM;
    int ar = tid >> 2, ac = (tid & 3) << 2;
    int br = tid >> 4, bc = (tid & 15) << 2;
    float acc[4][4] = {};

    for (int k0 = 0; k0 < K; k0 += TBK) {
        float4 av = *reinterpret_cast<const float4*>(A + (size_t)(m0 + ar) * K + k0 + ac);
        As[ac + 0][ar] = av.x; As[ac + 1][ar] = av.y;
        As[ac + 2][ar] = av.z; As[ac + 3][ar] = av.w;
        float4 bv = *reinterpret_cast<const float4*>(Bm + (size_t)(k0 + br) * N + n0 + bc);
        *reinterpret_cast<float4*>(&Bs[br][bc]) = bv;
        __syncthreads();
        #pragma unroll
        for (int k = 0; k < TBK; k++) {
            float a[4], bb[4];
            #pragma unroll
            for (int i = 0; i < 4; i++) a[i]  = As[k][ty * 4 + i];
            #pragma unroll
            for (int j = 0; j < 4; j++) bb[j] = Bs[k][tx * 4 + j];
            #pragma unroll
            for (int i = 0; i < 4; i++)
                #pragma unroll
                for (int j = 0; j < 4; j++) acc[i][j] += a[i] * bb[j];
        }
        __syncthreads();
    }

    #pragma unroll
    for (int i = 0; i < 4; i++) {
        int m = m0 + ty * 4 + i;
        if (MODE == 2) {
            float tr[Rr];
            #pragma unroll
            for (int r = 0; r < Rr; r++) tr[r] = g_t[(size_t)m * Rr + r];
            const float* wb_row = g_w + (size_t)m * W2N + (size_t)Dd * Rr;
            #pragma unroll
            for (int j = 0; j < 4; j++) {
                int n = n0 + tx * 4 + j;
                float4 w0 = *reinterpret_cast<const float4*>(wb_row + (size_t)n * Rr);
                float4 w1 = *reinterpret_cast<const float4*>(wb_row + (size_t)n * Rr + 4);
                float lr = tr[0]*w0.x + tr[1]*w0.y + tr[2]*w0.z + tr[3]*w0.w
                         + tr[4]*w1.x + tr[5]*w1.y + tr[6]*w1.z + tr[7]*w1.w;
                C[(size_t)m * N + n] = acc[i][j] + xres[(size_t)m * N + n] + lr;
            }
        } else {
            #pragma unroll
            for (int j = 0; j < 4; j++) {
                int n = n0 + tx * 4 + j;
                float v = acc[i][j] + bias[n];
                if (MODE == 0)
                    v = 0.5f * v * (1.f + erff(v * 0.70710678118654752f));
                C[(size_t)m * N + n] = v;
            }
        }
    }
}

// ---------------------------------------------------------------------------
// t[b,r] = sum_d x[b,d] * g_w[b, d*R + r]
// ---------------------------------------------------------------------------
__global__ void __launch_bounds__(256) t_kernel(const float* __restrict__ x)
{
    int b = blockIdx.x;
    const float* wrow = g_w + (size_t)b * W2N;
    const float* xrow = x + (size_t)b * Dd;
    float acc[Rr] = {};
    for (int d = threadIdx.x; d < Dd; d += blockDim.x) {
        float xv = xrow[d];
        float4 w0 = *reinterpret_cast<const float4*>(wrow + (size_t)d * Rr);
        float4 w1 = *reinterpret_cast<const float4*>(wrow + (size_t)d * Rr + 4);
        acc[0] += xv*w0.x; acc[1] += xv*w0.y; acc[2] += xv*w0.z; acc[3] += xv*w0.w;
        acc[4] += xv*w1.x; acc[5] += xv*w1.y; acc[6] += xv*w1.z; acc[7] += xv*w1.w;
    }
    #pragma unroll
    for (int o = 16; o; o >>= 1)
        #pragma unroll
        for (int r = 0; r < Rr; r++)
            acc[r] += __shfl_down_sync(0xFFFFFFFFu, acc[r], o);
    __shared__ float red[Rr][8];
    int wid = threadIdx.x >> 5, lid = threadIdx.x & 31;
    if (lid == 0)
        #pragma unroll
        for (int r = 0; r < Rr; r++) red[r][wid] = acc[r];
    __syncthreads();
    if (threadIdx.x < Rr) {
        int r = threadIdx.x;
        float s = 0.f;
        #pragma unroll
        for (int w = 0; w < 8; w++) s += red[r][w];
        g_t[(size_t)b * Rr + r] = s;
    }
}

// ---------------------------------------------------------------------------
// convert h (fp32 [B,K]) -> bf16 hi/lo (same layout)
// ---------------------------------------------------------------------------
__global__ void __launch_bounds__(256) convert_h_kernel()
{
    int i = (blockIdx.x * 256 + threadIdx.x) * 2;
    float v0 = g_h[i], v1 = g_h[i + 1];
    __nv_bfloat16 h0 = __float2bfloat16(v0), h1 = __float2bfloat16(v1);
    float l0 = v0 - __bfloat162float(h0), l1 = v1 - __bfloat162float(h1);
    *reinterpret_cast<__nv_bfloat162*>(&g_Ahi[i]) = __halves2bfloat162(h0, h1);
    *reinterpret_cast<__nv_bfloat162*>(&g_Alo[i]) =
        __halves2bfloat162(__float2bfloat16(l0), __float2bfloat16(l1));
}

// ---------------------------------------------------------------------------
// convert W2 fp32 [K,N] -> bf16 hi/lo [K,N], no transpose (streaming)
// ---------------------------------------------------------------------------
__global__ void __launch_bounds__(256) convert_w2_kernel(const float* __restrict__ W2)
{
    size_t i = ((size_t)blockIdx.x * 256 + threadIdx.x) * 4;
    float4 v = *reinterpret_cast<const float4*>(&W2[i]);
    __nv_bfloat16 h0 = __float2bfloat16(v.x), h1 = __float2bfloat16(v.y);
    __nv_bfloat16 h2 = __float2bfloat16(v.z), h3 = __float2bfloat16(v.w);
    float l0 = v.x - __bfloat162float(h0), l1 = v.y - __bfloat162float(h1);
    float l2 = v.z - __bfloat162float(h2), l3 = v.w - __bfloat162float(h3);
    __nv_bfloat162 hh0 = __halves2bfloat162(h0, h1);
    __nv_bfloat162 hh1 = __halves2bfloat162(h2, h3);
    __nv_bfloat162 ll0 = __halves2bfloat162(__float2bfloat16(l0), __float2bfloat16(l1));
    __nv_bfloat162 ll1 = __halves2bfloat162(__float2bfloat16(l2), __float2bfloat16(l3));
    *reinterpret_cast<__nv_bfloat162*>(&g_Whi[i]) = hh0;
    *reinterpret_cast<__nv_bfloat162*>(&g_Whi[i + 2]) = hh1;
    *reinterpret_cast<__nv_bfloat162*>(&g_Wlo[i]) = ll0;
    *reinterpret_cast<__nv_bfloat162*>(&g_Wlo[i + 2]) = ll1;
}

// ---------------------------------------------------------------------------
// GEMM2 via mma.sync bf16:  C[256,16384] = A[256,1024] @ W2[1024,16384] + b2
// A hi/lo k-major, W2 hi/lo [K,N]. 3-pass hi/lo split accumulated in fp32.
// CTA 128x128, BK=32, 8 warps (2m x 4n), each warp 64x32.
// ---------------------------------------------------------------------------
__device__ __forceinline__ void load_stage_g2(uint32_t sbase, int m0, int n0, int k0, int tid)
{
    // 2048 x 16B chunks: Ahi 512, Alo 512, Bhi 512, Blo 512
    #pragma unroll
    for (int it = 0; it < 8; it++) {
        int idx = tid + it * 256;
        if (idx < 512) {
            int row = idx >> 2, ch = idx & 3;
            cp_async16(sbase + OFF_AHI + row * (A_ROWLEN * 2) + ch * 16,
                       &g_Ahi[(size_t)(m0 + row) * Kd + k0 + ch * 8]);
        } else if (idx < 1024) {
            int l = idx - 512; int row = l >> 2, ch = l & 3;
            cp_async16(sbase + OFF_ALO + row * (A_ROWLEN * 2) + ch * 16,
                       &g_Alo[(size_t)(m0 + row) * Kd + k0 + ch * 8]);
        } else if (idx < 1536) {
            int l = idx - 1024; int row = l >> 4, ch = l & 15;
            cp_async16(sbase + OFF_BHI + row * (B_ROWLEN * 2) + ch * 16,
                       &g_Whi[(size_t)(k0 + row) * W2N + n0 + ch * 8]);
        } else {
            int l = idx - 1536; int row = l >> 4, ch = l & 15;
            cp_async16(sbase + OFF_BLO + row * (B_ROWLEN * 2) + ch * 16,
                       &g_Wlo[(size_t)(k0 + row) * W2N + n0 + ch * 8]);
        }
    }
}

__global__ void __launch_bounds__(256, 1) gemm2_mma_kernel(
    const float* __restrict__ b2, float* __restrict__ C)
{
    extern __shared__ char smem[];
    uint32_t sb = smem_u32(smem);
    const int tid = threadIdx.x, lane = tid & 31, wid = tid >> 5;
    const int warp_m = wid >> 2, warp_n = wid & 3;
    const int m0 = blockIdx.y * BM, n0 = blockIdx.x * BN;

    float acc[4][4][4];
    #pragma unroll
    for (int i = 0; i < 4; i++)
        #pragma unroll
        for (int j = 0; j < 4; j++)
            #pragma unroll
            for (int r = 0; r < 4; r++) acc[i][j][r] = 0.f;

    // bias fragment (per thread, per n-tile)
    float2 biasv[4];
    #pragma unroll
    for (int nt = 0; nt < 4; nt++)
        biasv[nt] = *reinterpret_cast<const float2*>(
            &b2[n0 + warp_n * 32 + nt * 8 + (lane & 3) * 2]);

    load_stage_g2(sb, m0, n0, 0, tid);               cp_commit();
    load_stage_g2(sb + STAGE_BYTES, m0, n0, BK, tid); cp_commit();

    // ldmatrix address components (constant per thread)
    const int a_row_in_tile = lane & 15;               // x4: rows 0..15
    const int a_colblk = (lane >> 4) << 3;             // 0 or 8 (k offset)
    const int b_row_in_tile = (lane & 7) + ((lane >> 3) & 1) * 8;  // x2: k 0..15
    const int b_ncol = warp_n * 32;                    // n base for this warp

    for (int kt = 0; kt < NKT; kt++) {
        if (kt == NKT - 1) cp_wait<0>(); else cp_wait<1>();
        __syncthreads();
        uint32_t base = sb + (kt & 1) * STAGE_BYTES;

        // ---- load all fragments for this k-tile ----
        uint32_t ah[2][4][4], al[2][4][4];   // [kstep][mtile][reg]
        uint32_t bh[2][4][2], bl[2][4][2];   // [kstep][ntile][reg]
        #pragma unroll
        for (int ks = 0; ks < 2; ks++) {
            #pragma unroll
            for (int mt = 0; mt < 4; mt++) {
                int row = warp_m * 64 + mt * 16 + a_row_in_tile;
                uint32_t off = (uint32_t)(row * A_ROWLEN + ks * 16 + a_colblk) * 2;
                ldsm_x4(ah[ks][mt][0], ah[ks][mt][1], ah[ks][mt][2], ah[ks][mt][3],
                        base + OFF_AHI + off);
                ldsm_x4(al[ks][mt][0], al[ks][mt][1], al[ks][mt][2], al[ks][mt][3],
                        base + OFF_ALO + off);
            }
            #pragma unroll
            for (int nt = 0; nt < 4; nt++) {
                int krow = ks * 16 + b_row_in_tile;
                uint32_t off = (uint32_t)(krow * B_ROWLEN + b_ncol + nt * 8) * 2;
                ldsm_x2_trans(bh[ks][nt][0], bh[ks][nt][1], base + OFF_BHI + off);
                ldsm_x2_trans(bl[ks][nt][0], bl[ks][nt][1], base + OFF_BLO + off);
            }
        }

        __syncthreads();   // all reads done before refill
        if (kt + 2 < NKT) {
            load_stage_g2(base, m0, n0, (kt + 2) * BK, tid);
            cp_commit();
        }

        // ---- 3-pass mma: hi*hi + hi*lo + lo*hi ----
        #pragma unroll
        for (int ks = 0; ks < 2; ks++)
            #pragma unroll
            for (int mt = 0; mt < 4; mt++)
                #pragma unroll
                for (int nt = 0; nt < 4; nt++) {
                    float* c = acc[mt][nt];
                    mma16816(c, ah[ks][mt][0], ah[ks][mt][1], ah[ks][mt][2], ah[ks][mt][3],
                             bh[ks][nt][0], bh[ks][nt][1]);
                    mma16816(c, ah[ks][mt][0], ah[ks][mt][1], ah[ks][mt][2], ah[ks][mt][3],
                             bl[ks][nt][0], bl[ks][nt][1]);
                    mma16816(c, al[ks][mt][0], al[ks][mt][1], al[ks][mt][2], al[ks][mt][3],
                             bh[ks][nt][0], bh[ks][nt][1]);
                }
    }

    // ---- epilogue: bias + store ----
    #pragma unroll
    for (int mt = 0; mt < 4; mt++) {
        int row0 = m0 + warp_m * 64 + mt * 16 + (lane >> 2);
        #pragma unroll
        for (int nt = 0; nt < 4; nt++) {
            int col = n0 + warp_n * 32 + nt * 8 + (lane & 3) * 2;
            float2 v0 = make_float2(acc[mt][nt][0] + biasv[nt].x,
                                    acc[mt][nt][1] + biasv[nt].y);
            float2 v1 = make_float2(acc[mt][nt][2] + biasv[nt].x,
                                    acc[mt][nt][3] + biasv[nt].y);
            *reinterpret_cast<float2*>(&C[(size_t)row0 * W2N + col]) = v0;
            *reinterpret_cast<float2*>(&C[(size_t)(row0 + 8) * W2N + col]) = v1;
        }
    }
}

// ---------------------------------------------------------------------------
extern "C" void kernel_launch(void* const* d_in, const int* in_sizes, int n_in,
                              void* d_out, int out_size)
{
    const float* x    = (const float*)d_in[0];
    const float* ada  = (const float*)d_in[1];
    const float* base = (const float*)d_in[2];
    const float* gam  = (const float*)d_in[3];
    const float* bet  = (const float*)d_in[4];
    const float* W1   = (const float*)d_in[5];
    const float* b1   = (const float*)d_in[6];
    const float* W2   = (const float*)d_in[7];
    const float* b2   = (const float*)d_in[8];
    float* out = (float*)d_out;

    float *cond_p, *h_p, *w_p;
    cudaGetSymbolAddress((void**)&cond_p, g_cond);
    cudaGetSymbolAddress((void**)&h_p, g_h);
    cudaGetSymbolAddress((void**)&w_p, g_w);

    cudaFuncSetAttribute(gemm2_mma_kernel,
                         cudaFuncAttributeMaxDynamicSharedMemorySize, SMEM_TOTAL);

    // W2 conversion (independent; largest prep)
    convert_w2_kernel<<<(Kd * W2N) / 1024, 256>>>(W2);

    // LayerNorm
    ln_kernel<<<Bsz, 256>>>(ada, gam, bet);

    // GEMM1: h = GELU(cond @ W1 + b1)
    sgemm_kernel<0><<<dim3(Ii / 64, Bsz / 64), 256>>>(cond_p, W1, b1, h_p, Ii, Aa, nullptr);

    // split h into bf16 hi/lo
    convert_h_kernel<<<(Bsz * Kd) / 512, 256>>>();

    // GEMM2 on tensor cores: w = h @ W2 + b2
    gemm2_mma_kernel<<<dim3(W2N / BN, Bsz / BM), 256, SMEM_TOTAL>>>(b2, w_p);

    // t and final GEMM3 + epilogue
    t_kernel<<<Bsz, 256>>>(x);
    sgemm_kernel<2><<<dim3(Dd / 64, Bsz / 64), 256>>>(x, base, nullptr, out, Dd, Aa, x);
}

// round 4
// speedup vs baseline: 1.5675x; 1.0226x over previous
#include <cuda_runtime.h>
#include <cuda_bf16.h>
#include <math.h>
#include <cstdint>

// ---------------------------------------------------------------------------
// AdaLoRAWithBase restructured:
//   out = x + x@base + sum_r t[b,r] * x_b[b,:,r],  t[b,r] = sum_c x[b,c]*x_a[b,c,r]
//   [x_a|x_b] = GELU(LN(ada)@W1+b1) @ W2 + b2
// GEMM2 (dominant) on mma.sync bf16 hi/lo 3-pass, with W2 fp32->bf16 conversion
// FUSED into the GEMM pipeline (no pre-convert pass over W2).
// ---------------------------------------------------------------------------

namespace {
constexpr int Bsz = 256;
constexpr int Dd  = 1024;
constexpr int Aa  = 1024;
constexpr int Ii  = 1024;
constexpr int Rr  = 8;
constexpr int W2N = Dd * Rr * 2;     // 16384
constexpr int Kd  = Ii;              // 1024

// GEMM2 tiling
constexpr int BM = 128, BN = 128, BK = 32;
constexpr int NKT = Kd / BK;         // 32 k-iterations
constexpr int PSTG = 5;              // cp.async stages

// per-stage smem layout (bytes)
constexpr int A_ROWLEN = 40;                         // bf16 elems per A row (pad)
constexpr int B_ROWLEN = 136;                        // bf16 elems per B row (pad)
constexpr int OFF2_AHI = 0;                          // 128*40*2  = 10240
constexpr int OFF2_ALO = 10240;                      // 10240
constexpr int OFF2_RAW = 20480;                      // 32*128*4  = 16384 (fp32 B)
constexpr int STAGE2   = 36864;
// converted bf16 B tiles (double buffered), after all stages
constexpr int OFF_BB   = PSTG * STAGE2;              // 184320
constexpr int BB_HALF  = 32 * B_ROWLEN * 2;          // 8704 (hi), lo at +8704
constexpr int BB_SZ    = 2 * BB_HALF;                // 17408 per buffer
constexpr int SMEM_TOTAL2 = OFF_BB + 2 * BB_SZ;      // 219136
}

// Scratch (device globals)
__device__ __align__(16) float g_cond[Bsz * Aa];
__device__ __align__(16) float g_h[Bsz * Ii];
__device__ __align__(16) float g_w[(size_t)Bsz * W2N];   // 16 MB
__device__ __align__(16) float g_t[Bsz * Rr];
__device__ __align__(16) __nv_bfloat16 g_Ahi[Bsz * Kd];
__device__ __align__(16) __nv_bfloat16 g_Alo[Bsz * Kd];

// ---------------------------------------------------------------------------
// PTX helpers (baseline sm_80+ only)
// ---------------------------------------------------------------------------
__device__ __forceinline__ uint32_t smem_u32(const void* p) {
    uint32_t a;
    asm("{ .reg .u64 t; cvta.to.shared.u64 t, %1; cvt.u32.u64 %0, t; }" : "=r"(a) : "l"(p));
    return a;
}
__device__ __forceinline__ void cp_async16(uint32_t saddr, const void* gaddr) {
    asm volatile("cp.async.cg.shared.global [%0], [%1], 16;" :: "r"(saddr), "l"(gaddr) : "memory");
}
__device__ __forceinline__ void cp_commit() {
    asm volatile("cp.async.commit_group;" ::: "memory");
}
template <int N>
__device__ __forceinline__ void cp_wait() {
    asm volatile("cp.async.wait_group %0;" :: "n"(N) : "memory");
}
__device__ __forceinline__ void ldsm_x4(uint32_t& r0, uint32_t& r1, uint32_t& r2, uint32_t& r3,
                                        uint32_t addr) {
    asm volatile("ldmatrix.sync.aligned.m8n8.x4.shared.b16 {%0,%1,%2,%3}, [%4];"
                 : "=r"(r0), "=r"(r1), "=r"(r2), "=r"(r3) : "r"(addr));
}
__device__ __forceinline__ void ldsm_x2_trans(uint32_t& r0, uint32_t& r1, uint32_t addr) {
    asm volatile("ldmatrix.sync.aligned.m8n8.x2.trans.shared.b16 {%0,%1}, [%2];"
                 : "=r"(r0), "=r"(r1) : "r"(addr));
}
__device__ __forceinline__ void mma16816(float* c, uint32_t a0, uint32_t a1, uint32_t a2,
                                         uint32_t a3, uint32_t b0, uint32_t b1) {
    asm volatile(
        "mma.sync.aligned.m16n8k16.row.col.f32.bf16.bf16.f32 "
        "{%0,%1,%2,%3},{%4,%5,%6,%7},{%8,%9},{%0,%1,%2,%3};"
        : "+f"(c[0]), "+f"(c[1]), "+f"(c[2]), "+f"(c[3])
        : "r"(a0), "r"(a1), "r"(a2), "r"(a3), "r"(b0), "r"(b1));
}

// ---------------------------------------------------------------------------
// LayerNorm
// ---------------------------------------------------------------------------
__global__ void __launch_bounds__(256) ln_kernel(
    const float* __restrict__ ada, const float* __restrict__ gamma,
    const float* __restrict__ beta)
{
    int b = blockIdx.x;
    const float* row = ada + (size_t)b * Aa;
    float s = 0.f, s2 = 0.f;
    for (int i = threadIdx.x; i < Aa; i += blockDim.x) {
        float v = row[i]; s += v; s2 += v * v;
    }
    #pragma unroll
    for (int o = 16; o; o >>= 1) {
        s  += __shfl_down_sync(0xFFFFFFFFu, s,  o);
        s2 += __shfl_down_sync(0xFFFFFFFFu, s2, o);
    }
    __shared__ float red0[8], red1[8], mv[2];
    int wid = threadIdx.x >> 5, lid = threadIdx.x & 31;
    if (lid == 0) { red0[wid] = s; red1[wid] = s2; }
    __syncthreads();
    if (threadIdx.x == 0) {
        float ts = 0.f, ts2 = 0.f;
        #pragma unroll
        for (int i = 0; i < 8; i++) { ts += red0[i]; ts2 += red1[i]; }
        float mu = ts * (1.f / Aa);
        float var = ts2 * (1.f / Aa) - mu * mu;
        mv[0] = mu; mv[1] = rsqrtf(var + 1e-5f);
    }
    __syncthreads();
    float mu = mv[0], rs = mv[1];
    for (int i = threadIdx.x; i < Aa; i += blockDim.x)
        g_cond[(size_t)b * Aa + i] = (row[i] - mu) * rs * gamma[i] + beta[i];
}

// ---------------------------------------------------------------------------
// fp32 SGEMM for GEMM1 (MODE 0: GELU) and GEMM3 (MODE 2: residual + rank-8)
// ---------------------------------------------------------------------------
template <int MODE>
__global__ void __launch_bounds__(256) sgemm_kernel(
    const float* __restrict__ A, const float* __restrict__ Bm,
    const float* __restrict__ bias, float* __restrict__ C,
    int N, int K, const float* __restrict__ xres)
{
    constexpr int TBM = 64, TBN = 64, TBK = 16;
    __shared__ float As[TBK][TBM];
    __shared__ float Bs[TBK][TBN];
    int tid = threadIdx.x;
    int tx = tid & 15, ty = tid >> 4;
    int n0 = blockIdx.x * TBN, m0 = blockIdx.y * TBM;
    int ar = tid >> 2, ac = (tid & 3) << 2;
    int br = tid >> 4, bc = (tid & 15) << 2;
    float acc[4][4] = {};

    for (int k0 = 0; k0 < K; k0 += TBK) {
        float4 av = *reinterpret_cast<const float4*>(A + (size_t)(m0 + ar) * K + k0 + ac);
        As[ac + 0][ar] = av.x; As[ac + 1][ar] = av.y;
        As[ac + 2][ar] = av.z; As[ac + 3][ar] = av.w;
        float4 bv = *reinterpret_cast<const float4*>(Bm + (size_t)(k0 + br) * N + n0 + bc);
        *reinterpret_cast<float4*>(&Bs[br][bc]) = bv;
        __syncthreads();
        #pragma unroll
        for (int k = 0; k < TBK; k++) {
            float a[4], bb[4];
            #pragma unroll
            for (int i = 0; i < 4; i++) a[i]  = As[k][ty * 4 + i];
            #pragma unroll
            for (int j = 0; j < 4; j++) bb[j] = Bs[k][tx * 4 + j];
            #pragma unroll
            for (int i = 0; i < 4; i++)
                #pragma unroll
                for (int j = 0; j < 4; j++) acc[i][j] += a[i] * bb[j];
        }
        __syncthreads();
    }

    #pragma unroll
    for (int i = 0; i < 4; i++) {
        int m = m0 + ty * 4 + i;
        if (MODE == 2) {
            float tr[Rr];
            #pragma unroll
            for (int r = 0; r < Rr; r++) tr[r] = g_t[(size_t)m * Rr + r];
            const float* wb_row = g_w + (size_t)m * W2N + (size_t)Dd * Rr;
            #pragma unroll
            for (int j = 0; j < 4; j++) {
                int n = n0 + tx * 4 + j;
                float4 w0 = *reinterpret_cast<const float4*>(wb_row + (size_t)n * Rr);
                float4 w1 = *reinterpret_cast<const float4*>(wb_row + (size_t)n * Rr + 4);
                float lr = tr[0]*w0.x + tr[1]*w0.y + tr[2]*w0.z + tr[3]*w0.w
                         + tr[4]*w1.x + tr[5]*w1.y + tr[6]*w1.z + tr[7]*w1.w;
                C[(size_t)m * N + n] = acc[i][j] + xres[(size_t)m * N + n] + lr;
            }
        } else {
            #pragma unroll
            for (int j = 0; j < 4; j++) {
                int n = n0 + tx * 4 + j;
                float v = acc[i][j] + bias[n];
                if (MODE == 0)
                    v = 0.5f * v * (1.f + erff(v * 0.70710678118654752f));
                C[(size_t)m * N + n] = v;
            }
        }
    }
}

// ---------------------------------------------------------------------------
// t[b,r] = sum_d x[b,d] * g_w[b, d*R + r]
// ---------------------------------------------------------------------------
__global__ void __launch_bounds__(256) t_kernel(const float* __restrict__ x)
{
    int b = blockIdx.x;
    const float* wrow = g_w + (size_t)b * W2N;
    const float* xrow = x + (size_t)b * Dd;
    float acc[Rr] = {};
    for (int d = threadIdx.x; d < Dd; d += blockDim.x) {
        float xv = xrow[d];
        float4 w0 = *reinterpret_cast<const float4*>(wrow + (size_t)d * Rr);
        float4 w1 = *reinterpret_cast<const float4*>(wrow + (size_t)d * Rr + 4);
        acc[0] += xv*w0.x; acc[1] += xv*w0.y; acc[2] += xv*w0.z; acc[3] += xv*w0.w;
        acc[4] += xv*w1.x; acc[5] += xv*w1.y; acc[6] += xv*w1.z; acc[7] += xv*w1.w;
    }
    #pragma unroll
    for (int o = 16; o; o >>= 1)
        #pragma unroll
        for (int r = 0; r < Rr; r++)
            acc[r] += __shfl_down_sync(0xFFFFFFFFu, acc[r], o);
    __shared__ float red[Rr][8];
    int wid = threadIdx.x >> 5, lid = threadIdx.x & 31;
    if (lid == 0)
        #pragma unroll
        for (int r = 0; r < Rr; r++) red[r][wid] = acc[r];
    __syncthreads();
    if (threadIdx.x < Rr) {
        int r = threadIdx.x;
        float s = 0.f;
        #pragma unroll
        for (int w = 0; w < 8; w++) s += red[r][w];
        g_t[(size_t)b * Rr + r] = s;
    }
}

// ---------------------------------------------------------------------------
// convert h (fp32 [B,K]) -> bf16 hi/lo (same layout)
// ---------------------------------------------------------------------------
__global__ void __launch_bounds__(256) convert_h_kernel()
{
    int i = (blockIdx.x * 256 + threadIdx.x) * 2;
    float v0 = g_h[i], v1 = g_h[i + 1];
    __nv_bfloat16 h0 = __float2bfloat16(v0), h1 = __float2bfloat16(v1);
    float l0 = v0 - __bfloat162float(h0), l1 = v1 - __bfloat162float(h1);
    *reinterpret_cast<__nv_bfloat162*>(&g_Ahi[i]) = __halves2bfloat162(h0, h1);
    *reinterpret_cast<__nv_bfloat162*>(&g_Alo[i]) =
        __halves2bfloat162(__float2bfloat16(l0), __float2bfloat16(l1));
}

// ---------------------------------------------------------------------------
// GEMM2 via mma.sync bf16 with fused W2 conversion:
//   C[256,16384] = A[256,1024] @ W2[1024,16384] + b2
// A hi/lo bf16 (pre-split). W2 loaded fp32, converted in-kernel to bf16 hi/lo
// one iteration ahead of consumption. 3-pass hi/lo split, fp32 accum.
// CTA 128x128, BK=32, 8 warps (2m x 4n), 5-stage cp.async pipeline.
// ---------------------------------------------------------------------------
__device__ __forceinline__ void load_group_g2(
    uint32_t sstage, const float* __restrict__ W2, int m0, int n0, int k0, int tid)
{
    // 2048 x 16B chunks: Ahi 512, Alo 512, raw B fp32 1024
    #pragma unroll
    for (int it = 0; it < 8; it++) {
        int idx = tid + it * 256;
        if (idx < 512) {
            int row = idx >> 2, ch = idx & 3;
            cp_async16(sstage + OFF2_AHI + row * (A_ROWLEN * 2) + ch * 16,
                       &g_Ahi[(size_t)(m0 + row) * Kd + k0 + ch * 8]);
        } else if (idx < 1024) {
            int l = idx - 512, row = l >> 2, ch = l & 3;
            cp_async16(sstage + OFF2_ALO + row * (A_ROWLEN * 2) + ch * 16,
                       &g_Alo[(size_t)(m0 + row) * Kd + k0 + ch * 8]);
        } else {
            int l = idx - 1024;              // 0..1023
            int row = l >> 5, ch = l & 31;   // 32 rows x 32 chunks (16B = 4 floats)
            cp_async16(sstage + OFF2_RAW + row * 512 + ch * 16,
                       &W2[(size_t)(k0 + row) * W2N + n0 + ch * 4]);
        }
    }
    cp_commit();
}

// convert one raw fp32 B stage (32x128) -> bf16 hi/lo tiles (B_ROWLEN layout)
__device__ __forceinline__ void convert_b_stage(
    char* smem, uint32_t raw_off, uint32_t bb_off, int tid)
{
    #pragma unroll
    for (int i = 0; i < 4; i++) {
        int c = tid + i * 256;                    // 16B chunk id, 0..1023
        float4 v = *reinterpret_cast<const float4*>(smem + raw_off + c * 16);
        int row = c >> 5;
        int col = (c & 31) * 4;
        __nv_bfloat16 h0 = __float2bfloat16(v.x), h1 = __float2bfloat16(v.y);
        __nv_bfloat16 h2 = __float2bfloat16(v.z), h3 = __float2bfloat16(v.w);
        float l0 = v.x - __bfloat162float(h0), l1 = v.y - __bfloat162float(h1);
        float l2 = v.z - __bfloat162float(h2), l3 = v.w - __bfloat162float(h3);
        uint32_t eoff = (uint32_t)(row * B_ROWLEN + col) * 2;
        char* hi = smem + bb_off + eoff;
        char* lo = smem + bb_off + BB_HALF + eoff;
        *reinterpret_cast<__nv_bfloat162*>(hi)     = __halves2bfloat162(h0, h1);
        *reinterpret_cast<__nv_bfloat162*>(hi + 4) = __halves2bfloat162(h2, h3);
        *reinterpret_cast<__nv_bfloat162*>(lo)     =
            __halves2bfloat162(__float2bfloat16(l0), __float2bfloat16(l1));
        *reinterpret_cast<__nv_bfloat162*>(lo + 4) =
            __halves2bfloat162(__float2bfloat16(l2), __float2bfloat16(l3));
    }
}

__global__ void __launch_bounds__(256, 1) gemm2_mma_kernel(
    const float* __restrict__ W2, const float* __restrict__ b2, float* __restrict__ C)
{
    extern __shared__ char smem[];
    uint32_t sb = smem_u32(smem);
    const int tid = threadIdx.x, lane = tid & 31, wid = tid >> 5;
    const int warp_m = wid >> 2, warp_n = wid & 3;
    const int m0 = blockIdx.y * BM, n0 = blockIdx.x * BN;

    float acc[4][4][4];
    #pragma unroll
    for (int i = 0; i < 4; i++)
        #pragma unroll
        for (int j = 0; j < 4; j++)
            #pragma unroll
            for (int r = 0; r < 4; r++) acc[i][j][r] = 0.f;

    float2 biasv[4];
    #pragma unroll
    for (int nt = 0; nt < 4; nt++)
        biasv[nt] = *reinterpret_cast<const float2*>(
            &b2[n0 + warp_n * 32 + nt * 8 + (lane & 3) * 2]);

    // prologue: issue 4 stage-groups
    #pragma unroll
    for (int s = 0; s < PSTG - 1; s++)
        load_group_g2(sb + s * STAGE2, W2, m0, n0, s * BK, tid);

    // pre-convert stage 0 -> bb0
    cp_wait<3>();
    __syncthreads();
    convert_b_stage(smem, OFF2_RAW, OFF_BB, tid);

    const int a_row_in_tile = lane & 15;
    const int a_colblk = (lane >> 4) << 3;
    const int b_row_in_tile = (lane & 7) + ((lane >> 3) & 1) * 8;
    const int b_ncol = warp_n * 32;

    for (int kt = 0; kt < NKT; kt++) {
        cp_wait<2>();          // group kt+1 arrived
        __syncthreads();       // prev-iter reads done; prev convert visible

        if (kt + PSTG - 1 < NKT)
            load_group_g2(sb + ((kt + PSTG - 1) % PSTG) * STAGE2, W2,
                          m0, n0, (kt + PSTG - 1) * BK, tid);
        if (kt + 1 < NKT)
            convert_b_stage(smem, ((kt + 1) % PSTG) * STAGE2 + OFF2_RAW,
                            OFF_BB + ((kt + 1) & 1) * BB_SZ, tid);

        uint32_t abase = sb + (kt % PSTG) * STAGE2;
        uint32_t bbase = sb + OFF_BB + (kt & 1) * BB_SZ;

        #pragma unroll
        for (int ks = 0; ks < 2; ks++) {
            uint32_t ah[4][4], al[4][4], bh[4][2], bl[4][2];
            #pragma unroll
            for (int mt = 0; mt < 4; mt++) {
                int row = warp_m * 64 + mt * 16 + a_row_in_tile;
                uint32_t off = (uint32_t)(row * A_ROWLEN + ks * 16 + a_colblk) * 2;
                ldsm_x4(ah[mt][0], ah[mt][1], ah[mt][2], ah[mt][3], abase + OFF2_AHI + off);
                ldsm_x4(al[mt][0], al[mt][1], al[mt][2], al[mt][3], abase + OFF2_ALO + off);
            }
            #pragma unroll
            for (int nt = 0; nt < 4; nt++) {
                int krow = ks * 16 + b_row_in_tile;
                uint32_t off = (uint32_t)(krow * B_ROWLEN + b_ncol + nt * 8) * 2;
                ldsm_x2_trans(bh[nt][0], bh[nt][1], bbase + off);
                ldsm_x2_trans(bl[nt][0], bl[nt][1], bbase + BB_HALF + off);
            }
            // pass 1: hi*hi
            #pragma unroll
            for (int mt = 0; mt < 4; mt++)
                #pragma unroll
                for (int nt = 0; nt < 4; nt++)
                    mma16816(acc[mt][nt], ah[mt][0], ah[mt][1], ah[mt][2], ah[mt][3],
                             bh[nt][0], bh[nt][1]);
            // pass 2: hi*lo
            #pragma unroll
            for (int mt = 0; mt < 4; mt++)
                #pragma unroll
                for (int nt = 0; nt < 4; nt++)
                    mma16816(acc[mt][nt], ah[mt][0], ah[mt][1], ah[mt][2], ah[mt][3],
                             bl[nt][0], bl[nt][1]);
            // pass 3: lo*hi
            #pragma unroll
            for (int mt = 0; mt < 4; mt++)
                #pragma unroll
                for (int nt = 0; nt < 4; nt++)
                    mma16816(acc[mt][nt], al[mt][0], al[mt][1], al[mt][2], al[mt][3],
                             bh[nt][0], bh[nt][1]);
        }
    }

    // epilogue: bias + store
    #pragma unroll
    for (int mt = 0; mt < 4; mt++) {
        int row0 = m0 + warp_m * 64 + mt * 16 + (lane >> 2);
        #pragma unroll
        for (int nt = 0; nt < 4; nt++) {
            int col = n0 + warp_n * 32 + nt * 8 + (lane & 3) * 2;
            float2 v0 = make_float2(acc[mt][nt][0] + biasv[nt].x,
                                    acc[mt][nt][1] + biasv[nt].y);
            float2 v1 = make_float2(acc[mt][nt][2] + biasv[nt].x,
                                    acc[mt][nt][3] + biasv[nt].y);
            *reinterpret_cast<float2*>(&C[(size_t)row0 * W2N + col]) = v0;
            *reinterpret_cast<float2*>(&C[(size_t)(row0 + 8) * W2N + col]) = v1;
        }
    }
}

// ---------------------------------------------------------------------------
extern "C" void kernel_launch(void* const* d_in, const int* in_sizes, int n_in,
                              void* d_out, int out_size)
{
    const float* x    = (const float*)d_in[0];
    const float* ada  = (const float*)d_in[1];
    const float* base = (const float*)d_in[2];
    const float* gam  = (const float*)d_in[3];
    const float* bet  = (const float*)d_in[4];
    const float* W1   = (const float*)d_in[5];
    const float* b1   = (const float*)d_in[6];
    const float* W2   = (const float*)d_in[7];
    const float* b2   = (const float*)d_in[8];
    float* out = (float*)d_out;

    float *cond_p, *h_p, *w_p;
    cudaGetSymbolAddress((void**)&cond_p, g_cond);
    cudaGetSymbolAddress((void**)&h_p, g_h);
    cudaGetSymbolAddress((void**)&w_p, g_w);

    cudaFuncSetAttribute(gemm2_mma_kernel,
                         cudaFuncAttributeMaxDynamicSharedMemorySize, SMEM_TOTAL2);

    // LayerNorm
    ln_kernel<<<Bsz, 256>>>(ada, gam, bet);

    // GEMM1: h = GELU(cond @ W1 + b1)
    sgemm_kernel<0><<<dim3(Ii / 64, Bsz / 64), 256>>>(cond_p, W1, b1, h_p, Ii, Aa, nullptr);

    // split h into bf16 hi/lo
    convert_h_kernel<<<(Bsz * Kd) / 512, 256>>>();

    // GEMM2 on tensor cores with fused W2 conversion: w = h @ W2 + b2
    gemm2_mma_kernel<<<dim3(W2N / BN, Bsz / BM), 256, SMEM_TOTAL2>>>(W2, b2, w_p);

    // t and final GEMM3 + epilogue
    t_kernel<<<Bsz, 256>>>(x);
    sgemm_kernel<2><<<dim3(Dd / 64, Bsz / 64), 256>>>(x, base, nullptr, out, Dd, Aa, x);
}

// round 5
// speedup vs baseline: 1.8620x; 1.1878x over previous
#include <cuda_runtime.h>
#include <cuda_bf16.h>
#include <math.h>
#include <cstdint>

// ---------------------------------------------------------------------------
// AdaLoRAWithBase restructured:
//   out = x + x@base + sum_r t[b,r] * x_b[b,:,r],  t[b,r] = sum_c x[b,c]*x_a[b,c,r]
//   [x_a|x_b] = GELU(LN(ada)@W1+b1) @ W2 + b2
// ALL three GEMMs on mma.sync bf16 hi/lo 3-pass with fused fp32->bf16 B
// conversion. GEMM1/GEMM3 use split-K=4 (grid 128) + fused reduce epilogues.
// ---------------------------------------------------------------------------

namespace {
constexpr int Bsz = 256;
constexpr int Dd  = 1024;
constexpr int Aa  = 1024;
constexpr int Rr  = 8;
constexpr int W2N = Dd * Rr * 2;     // 16384
constexpr int Kd  = 1024;

constexpr int BM = 128, BK = 32;
constexpr int PSTG = 5;
constexpr int A_ROWB = 80;           // bytes per A smem row (40 bf16, conflict-free)
}

// Scratch (device globals)
__device__ __align__(16) float g_w[(size_t)Bsz * W2N];   // 16 MB
__device__ __align__(16) float g_t[Bsz * Rr];
__device__ __align__(16) float g_p1[4 * Bsz * Dd];       // gemm1 split-K partials
__device__ __align__(16) float g_p3[4 * Bsz * Dd];       // gemm3 split-K partials
__device__ __align__(16) __nv_bfloat16 g_Chi[Bsz * Kd];  // LN(ada) hi/lo
__device__ __align__(16) __nv_bfloat16 g_Clo[Bsz * Kd];
__device__ __align__(16) __nv_bfloat16 g_Ahi[Bsz * Kd];  // h hi/lo (gemm2 A)
__device__ __align__(16) __nv_bfloat16 g_Alo[Bsz * Kd];
__device__ __align__(16) __nv_bfloat16 g_Xhi[Bsz * Kd];  // x hi/lo (gemm3 A)
__device__ __align__(16) __nv_bfloat16 g_Xlo[Bsz * Kd];

// ---------------------------------------------------------------------------
// PTX helpers (baseline sm_80+ only)
// ---------------------------------------------------------------------------
__device__ __forceinline__ uint32_t smem_u32(const void* p) {
    uint32_t a;
    asm("{ .reg .u64 t; cvta.to.shared.u64 t, %1; cvt.u32.u64 %0, t; }" : "=r"(a) : "l"(p));
    return a;
}
__device__ __forceinline__ void cp_async16(uint32_t saddr, const void* gaddr) {
    asm volatile("cp.async.cg.shared.global [%0], [%1], 16;" :: "r"(saddr), "l"(gaddr) : "memory");
}
__device__ __forceinline__ void cp_commit() {
    asm volatile("cp.async.commit_group;" ::: "memory");
}
template <int N>
__device__ __forceinline__ void cp_wait() {
    asm volatile("cp.async.wait_group %0;" :: "n"(N) : "memory");
}
__device__ __forceinline__ void ldsm_x4(uint32_t& r0, uint32_t& r1, uint32_t& r2, uint32_t& r3,
                                        uint32_t addr) {
    asm volatile("ldmatrix.sync.aligned.m8n8.x4.shared.b16 {%0,%1,%2,%3}, [%4];"
                 : "=r"(r0), "=r"(r1), "=r"(r2), "=r"(r3) : "r"(addr));
}
__device__ __forceinline__ void ldsm_x2_trans(uint32_t& r0, uint32_t& r1, uint32_t addr) {
    asm volatile("ldmatrix.sync.aligned.m8n8.x2.trans.shared.b16 {%0,%1}, [%2];"
                 : "=r"(r0), "=r"(r1) : "r"(addr));
}
__device__ __forceinline__ void mma16816(float* c, uint32_t a0, uint32_t a1, uint32_t a2,
                                         uint32_t a3, uint32_t b0, uint32_t b1) {
    asm volatile(
        "mma.sync.aligned.m16n8k16.row.col.f32.bf16.bf16.f32 "
        "{%0,%1,%2,%3},{%4,%5,%6,%7},{%8,%9},{%0,%1,%2,%3};"
        : "+f"(c[0]), "+f"(c[1]), "+f"(c[2]), "+f"(c[3])
        : "r"(a0), "r"(a1), "r"(a2), "r"(a3), "r"(b0), "r"(b1));
}

// ---------------------------------------------------------------------------
// LayerNorm -> bf16 hi/lo split directly (feeds GEMM1 A)
// ---------------------------------------------------------------------------
__global__ void __launch_bounds__(256) ln_kernel(
    const float* __restrict__ ada, const float* __restrict__ gamma,
    const float* __restrict__ beta)
{
    int b = blockIdx.x;
    const float* row = ada + (size_t)b * Aa;
    float s = 0.f, s2 = 0.f;
    for (int i = threadIdx.x; i < Aa; i += blockDim.x) {
        float v = row[i]; s += v; s2 += v * v;
    }
    #pragma unroll
    for (int o = 16; o; o >>= 1) {
        s  += __shfl_down_sync(0xFFFFFFFFu, s,  o);
        s2 += __shfl_down_sync(0xFFFFFFFFu, s2, o);
    }
    __shared__ float red0[8], red1[8], mv[2];
    int wid = threadIdx.x >> 5, lid = threadIdx.x & 31;
    if (lid == 0) { red0[wid] = s; red1[wid] = s2; }
    __syncthreads();
    if (threadIdx.x == 0) {
        float ts = 0.f, ts2 = 0.f;
        #pragma unroll
        for (int i = 0; i < 8; i++) { ts += red0[i]; ts2 += red1[i]; }
        float mu = ts * (1.f / Aa);
        float var = ts2 * (1.f / Aa) - mu * mu;
        mv[0] = mu; mv[1] = rsqrtf(var + 1e-5f);
    }
    __syncthreads();
    float mu = mv[0], rs = mv[1];
    for (int i = threadIdx.x; i < Aa; i += blockDim.x) {
        float v = (row[i] - mu) * rs * gamma[i] + beta[i];
        __nv_bfloat16 hi = __float2bfloat16(v);
        g_Chi[(size_t)b * Aa + i] = hi;
        g_Clo[(size_t)b * Aa + i] = __float2bfloat16(v - __bfloat162float(hi));
    }
}

// ---------------------------------------------------------------------------
// convert fp32 -> bf16 hi/lo (for x)
// ---------------------------------------------------------------------------
__global__ void __launch_bounds__(256) convert_split_kernel(
    const float* __restrict__ src, __nv_bfloat16* __restrict__ hi,
    __nv_bfloat16* __restrict__ lo)
{
    int i = (blockIdx.x * 256 + threadIdx.x) * 2;
    float v0 = src[i], v1 = src[i + 1];
    __nv_bfloat16 h0 = __float2bfloat16(v0), h1 = __float2bfloat16(v1);
    float l0 = v0 - __bfloat162float(h0), l1 = v1 - __bfloat162float(h1);
    *reinterpret_cast<__nv_bfloat162*>(&hi[i]) = __halves2bfloat162(h0, h1);
    *reinterpret_cast<__nv_bfloat162*>(&lo[i]) =
        __halves2bfloat162(__float2bfloat16(l0), __float2bfloat16(l1));
}

// ---------------------------------------------------------------------------
// t[b,r] = sum_d x[b,d] * g_w[b, d*R + r]
// ---------------------------------------------------------------------------
__global__ void __launch_bounds__(256) t_kernel(const float* __restrict__ x)
{
    int b = blockIdx.x;
    const float* wrow = g_w + (size_t)b * W2N;
    const float* xrow = x + (size_t)b * Dd;
    float acc[Rr] = {};
    for (int d = threadIdx.x; d < Dd; d += blockDim.x) {
        float xv = xrow[d];
        float4 w0 = *reinterpret_cast<const float4*>(wrow + (size_t)d * Rr);
        float4 w1 = *reinterpret_cast<const float4*>(wrow + (size_t)d * Rr + 4);
        acc[0] += xv*w0.x; acc[1] += xv*w0.y; acc[2] += xv*w0.z; acc[3] += xv*w0.w;
        acc[4] += xv*w1.x; acc[5] += xv*w1.y; acc[6] += xv*w1.z; acc[7] += xv*w1.w;
    }
    #pragma unroll
    for (int o = 16; o; o >>= 1)
        #pragma unroll
        for (int r = 0; r < Rr; r++)
            acc[r] += __shfl_down_sync(0xFFFFFFFFu, acc[r], o);
    __shared__ float red[Rr][8];
    int wid = threadIdx.x >> 5, lid = threadIdx.x & 31;
    if (lid == 0)
        #pragma unroll
        for (int r = 0; r < Rr; r++) red[r][wid] = acc[r];
    __syncthreads();
    if (threadIdx.x < Rr) {
        int r = threadIdx.x;
        float s = 0.f;
        #pragma unroll
        for (int w = 0; w < 8; w++) s += red[r][w];
        g_t[(size_t)b * Rr + r] = s;
    }
}

// ---------------------------------------------------------------------------
// Unified bf16 hi/lo 3-pass MMA GEMM with fused fp32 B conversion.
//   C[256, N_] (+bias) = A[256, 1024] @ Braw[1024, N_]
// BM=128, BK=32, 8 warps (2m x 4n). Split-K via blockIdx.z (partials to C+z*M*N).
// smem per stage: Ahi(10240) + Alo(10240) + rawB(32*N_*... 128*BN_).
// ---------------------------------------------------------------------------
template <int BN_, int N_>
__device__ __forceinline__ void load_grp(
    uint32_t sstage, const __nv_bfloat16* __restrict__ ahi,
    const __nv_bfloat16* __restrict__ alo, const float* __restrict__ Braw,
    int m0, int n0, int k0, int tid)
{
    constexpr int RCHR = BN_ / 4;            // 16B chunks per raw row
    constexpr int TOT = 1024 + 8 * BN_;      // total 16B chunks per stage
    #pragma unroll
    for (int it = 0; it < TOT / 256; it++) {
        int idx = tid + it * 256;
        if (idx < 512) {
            int row = idx >> 2, ch = idx & 3;
            cp_async16(sstage + row * A_ROWB + ch * 16,
                       &ahi[(size_t)(m0 + row) * Kd + k0 + ch * 8]);
        } else if (idx < 1024) {
            int l = idx - 512, row = l >> 2, ch = l & 3;
            cp_async16(sstage + 10240 + row * A_ROWB + ch * 16,
                       &alo[(size_t)(m0 + row) * Kd + k0 + ch * 8]);
        } else {
            int l = idx - 1024;
            int row = l / RCHR, ch = l % RCHR;
            cp_async16(sstage + 20480 + row * (BN_ * 4) + ch * 16,
                       &Braw[(size_t)(k0 + row) * N_ + n0 + ch * 4]);
        }
    }
    cp_commit();
}

template <int BN_>
__device__ __forceinline__ void conv_b(char* smem, uint32_t raw_off, uint32_t bb_off,
                                       uint32_t bb_half, int tid)
{
    constexpr int B_RL = BN_ + 8;
    constexpr int RC = 8 * BN_;              // float4 chunks in raw tile
    #pragma unroll
    for (int i = 0; i < RC / 256; i++) {
        int c = tid + i * 256;
        float4 v = *reinterpret_cast<const float4*>(smem + raw_off + c * 16);
        int row = c / (BN_ / 4);
        int col = (c % (BN_ / 4)) * 4;
        __nv_bfloat16 h0 = __float2bfloat16(v.x), h1 = __float2bfloat16(v.y);
        __nv_bfloat16 h2 = __float2bfloat16(v.z), h3 = __float2bfloat16(v.w);
        float l0 = v.x - __bfloat162float(h0), l1 = v.y - __bfloat162float(h1);
        float l2 = v.z - __bfloat162float(h2), l3 = v.w - __bfloat162float(h3);
        uint32_t eoff = (uint32_t)(row * B_RL + col) * 2;
        char* hi = smem + bb_off + eoff;
        char* lo = smem + bb_off + bb_half + eoff;
        *reinterpret_cast<__nv_bfloat162*>(hi)     = __halves2bfloat162(h0, h1);
        *reinterpret_cast<__nv_bfloat162*>(hi + 4) = __halves2bfloat162(h2, h3);
        *reinterpret_cast<__nv_bfloat162*>(lo)     =
            __halves2bfloat162(__float2bfloat16(l0), __float2bfloat16(l1));
        *reinterpret_cast<__nv_bfloat162*>(lo + 4) =
            __halves2bfloat162(__float2bfloat16(l2), __float2bfloat16(l3));
    }
}

template <int BN_, int SK, bool HAS_BIAS, int N_>
__global__ void __launch_bounds__(256, 1) gemm_mma_kernel(
    const __nv_bfloat16* __restrict__ ahi, const __nv_bfloat16* __restrict__ alo,
    const float* __restrict__ Braw, const float* __restrict__ bias,
    float* __restrict__ C)
{
    constexpr int NT = BN_ / 32;
    constexpr int B_RL = BN_ + 8;
    constexpr int STG = 20480 + 128 * BN_;
    constexpr int OFF_BBc = PSTG * STG;
    constexpr int BB_HALFc = 32 * B_RL * 2;
    constexpr int BB_SZc = 2 * BB_HALFc;
    constexpr int KITERS = Kd / SK / BK;

    extern __shared__ char smem[];
    uint32_t sb = smem_u32(smem);
    const int tid = threadIdx.x, lane = tid & 31, wid = tid >> 5;
    const int warp_m = wid >> 2, warp_n = wid & 3;
    const int m0 = blockIdx.y * BM, n0 = blockIdx.x * BN_;
    const int kb = blockIdx.z * (Kd / SK);

    float acc[4][NT][4];
    #pragma unroll
    for (int i = 0; i < 4; i++)
        #pragma unroll
        for (int j = 0; j < NT; j++)
            #pragma unroll
            for (int r = 0; r < 4; r++) acc[i][j][r] = 0.f;

    float2 biasv[NT];
    if constexpr (HAS_BIAS) {
        #pragma unroll
        for (int nt = 0; nt < NT; nt++)
            biasv[nt] = *reinterpret_cast<const float2*>(
                &bias[n0 + warp_n * (BN_ / 4) + nt * 8 + (lane & 3) * 2]);
    }

    #pragma unroll
    for (int s = 0; s < PSTG - 1; s++)
        load_grp<BN_, N_>(sb + s * STG, ahi, alo, Braw, m0, n0, kb + s * BK, tid);

    cp_wait<3>();
    __syncthreads();
    conv_b<BN_>(smem, 20480, OFF_BBc, BB_HALFc, tid);

    const int a_row_in_tile = lane & 15;
    const int a_colblk = (lane >> 4) << 3;
    const int b_row_in_tile = (lane & 7) + ((lane >> 3) & 1) * 8;
    const int b_ncol = warp_n * (BN_ / 4);

    for (int kt = 0; kt < KITERS; kt++) {
        cp_wait<2>();
        __syncthreads();

        if (kt + PSTG - 1 < KITERS)
            load_grp<BN_, N_>(sb + ((kt + PSTG - 1) % PSTG) * STG, ahi, alo, Braw,
                              m0, n0, kb + (kt + PSTG - 1) * BK, tid);
        if (kt + 1 < KITERS)
            conv_b<BN_>(smem, ((kt + 1) % PSTG) * STG + 20480,
                        OFF_BBc + ((kt + 1) & 1) * BB_SZc, BB_HALFc, tid);

        uint32_t abase = sb + (kt % PSTG) * STG;
        uint32_t bbase = sb + OFF_BBc + (kt & 1) * BB_SZc;

        #pragma unroll
        for (int ks = 0; ks < 2; ks++) {
            uint32_t ah[4][4], al[4][4], bh[NT][2], bl[NT][2];
            #pragma unroll
            for (int mt = 0; mt < 4; mt++) {
                int row = warp_m * 64 + mt * 16 + a_row_in_tile;
                uint32_t off = (uint32_t)(row * 40 + ks * 16 + a_colblk) * 2;
                ldsm_x4(ah[mt][0], ah[mt][1], ah[mt][2], ah[mt][3], abase + off);
                ldsm_x4(al[mt][0], al[mt][1], al[mt][2], al[mt][3], abase + 10240 + off);
            }
            #pragma unroll
            for (int nt = 0; nt < NT; nt++) {
                int krow = ks * 16 + b_row_in_tile;
                uint32_t off = (uint32_t)(krow * B_RL + b_ncol + nt * 8) * 2;
                ldsm_x2_trans(bh[nt][0], bh[nt][1], bbase + off);
                ldsm_x2_trans(bl[nt][0], bl[nt][1], bbase + BB_HALFc + off);
            }
            #pragma unroll
            for (int mt = 0; mt < 4; mt++)
                #pragma unroll
                for (int nt = 0; nt < NT; nt++)
                    mma16816(acc[mt][nt], ah[mt][0], ah[mt][1], ah[mt][2], ah[mt][3],
                             bh[nt][0], bh[nt][1]);
            #pragma unroll
            for (int mt = 0; mt < 4; mt++)
                #pragma unroll
                for (int nt = 0; nt < NT; nt++)
                    mma16816(acc[mt][nt], ah[mt][0], ah[mt][1], ah[mt][2], ah[mt][3],
                             bl[nt][0], bl[nt][1]);
            #pragma unroll
            for (int mt = 0; mt < 4; mt++)
                #pragma unroll
                for (int nt = 0; nt < NT; nt++)
                    mma16816(acc[mt][nt], al[mt][0], al[mt][1], al[mt][2], al[mt][3],
                             bh[nt][0], bh[nt][1]);
        }
    }

    float* Cw = C + (size_t)blockIdx.z * Bsz * N_;
    #pragma unroll
    for (int mt = 0; mt < 4; mt++) {
        int row0 = m0 + warp_m * 64 + mt * 16 + (lane >> 2);
        #pragma unroll
        for (int nt = 0; nt < NT; nt++) {
            int col = n0 + warp_n * (BN_ / 4) + nt * 8 + (lane & 3) * 2;
            float bx = 0.f, by = 0.f;
            if constexpr (HAS_BIAS) { bx = biasv[nt].x; by = biasv[nt].y; }
            float2 v0 = make_float2(acc[mt][nt][0] + bx, acc[mt][nt][1] + by);
            float2 v1 = make_float2(acc[mt][nt][2] + bx, acc[mt][nt][3] + by);
            *reinterpret_cast<float2*>(&Cw[(size_t)row0 * N_ + col]) = v0;
            *reinterpret_cast<float2*>(&Cw[(size_t)(row0 + 8) * N_ + col]) = v1;
        }
    }
}

// ---------------------------------------------------------------------------
// reduce1: h = GELU(sum_z p1[z] + b1) -> bf16 hi/lo (gemm2 A operand)
// ---------------------------------------------------------------------------
__global__ void __launch_bounds__(256) reduce1_kernel(const float* __restrict__ b1)
{
    int e = (blockIdx.x * 256 + threadIdx.x) * 4;
    float4 s = *reinterpret_cast<const float4*>(&g_p1[e]);
    #pragma unroll
    for (int z = 1; z < 4; z++) {
        float4 p = *reinterpret_cast<const float4*>(&g_p1[z * (Bsz * Dd) + e]);
        s.x += p.x; s.y += p.y; s.z += p.z; s.w += p.w;
    }
    float4 bb = *reinterpret_cast<const float4*>(&b1[e & (Dd - 1)]);
    float u[4] = {s.x + bb.x, s.y + bb.y, s.z + bb.z, s.w + bb.w};
    __nv_bfloat16 hi[4], lo[4];
    #pragma unroll
    for (int i = 0; i < 4; i++) {
        float g = 0.5f * u[i] * (1.f + erff(u[i] * 0.70710678118654752f));
        hi[i] = __float2bfloat16(g);
        lo[i] = __float2bfloat16(g - __bfloat162float(hi[i]));
    }
    *reinterpret_cast<__nv_bfloat162*>(&g_Ahi[e])     = __halves2bfloat162(hi[0], hi[1]);
    *reinterpret_cast<__nv_bfloat162*>(&g_Ahi[e + 2]) = __halves2bfloat162(hi[2], hi[3]);
    *reinterpret_cast<__nv_bfloat162*>(&g_Alo[e])     = __halves2bfloat162(lo[0], lo[1]);
    *reinterpret_cast<__nv_bfloat162*>(&g_Alo[e + 2]) = __halves2bfloat162(lo[2], lo[3]);
}

// ---------------------------------------------------------------------------
// reduce3: out[b,o] = x[b,o] + sum_z p3[z][b,o] + sum_r t[b,r]*g_w[b, D*R + o*R + r]
// ---------------------------------------------------------------------------
__global__ void __launch_bounds__(256) reduce3_kernel(
    const float* __restrict__ x, float* __restrict__ out)
{
    int b = blockIdx.y;
    int o = blockIdx.x * 512 + threadIdx.x * 2;
    size_t e = (size_t)b * Dd + o;
    float2 s = *reinterpret_cast<const float2*>(&x[e]);
    #pragma unroll
    for (int z = 0; z < 4; z++) {
        float2 p = *reinterpret_cast<const float2*>(&g_p3[z * (Bsz * Dd) + e]);
        s.x += p.x; s.y += p.y;
    }
    const float* tr = &g_t[b * Rr];
    float t0 = tr[0], t1 = tr[1], t2 = tr[2], t3 = tr[3];
    float t4 = tr[4], t5 = tr[5], t6 = tr[6], t7 = tr[7];
    const float* wb = &g_w[(size_t)b * W2N + (size_t)Dd * Rr + (size_t)o * Rr];
    float4 w0 = *reinterpret_cast<const float4*>(wb);
    float4 w1 = *reinterpret_cast<const float4*>(wb + 4);
    float4 w2 = *reinterpret_cast<const float4*>(wb + 8);
    float4 w3 = *reinterpret_cast<const float4*>(wb + 12);
    float lr0 = t0*w0.x + t1*w0.y + t2*w0.z + t3*w0.w
              + t4*w1.x + t5*w1.y + t6*w1.z + t7*w1.w;
    float lr1 = t0*w2.x + t1*w2.y + t2*w2.z + t3*w2.w
              + t4*w3.x + t5*w3.y + t6*w3.z + t7*w3.w;
    *reinterpret_cast<float2*>(&out[e]) = make_float2(s.x + lr0, s.y + lr1);
}

// ---------------------------------------------------------------------------
extern "C" void kernel_launch(void* const* d_in, const int* in_sizes, int n_in,
                              void* d_out, int out_size)
{
    const float* x    = (const float*)d_in[0];
    const float* ada  = (const float*)d_in[1];
    const float* base = (const float*)d_in[2];
    const float* gam  = (const float*)d_in[3];
    const float* bet  = (const float*)d_in[4];
    const float* W1   = (const float*)d_in[5];
    const float* b1   = (const float*)d_in[6];
    const float* W2   = (const float*)d_in[7];
    const float* b2   = (const float*)d_in[8];
    float* out = (float*)d_out;

    // smem sizes per instantiation
    constexpr int SMEM64  = PSTG * (20480 + 128 * 64)  + 2 * (2 * 32 * 72 * 2);   // 161792
    constexpr int SMEM128 = PSTG * (20480 + 128 * 128) + 2 * (2 * 32 * 136 * 2);  // 219136

    float *w_p, *p1_p, *p3_p;
    __nv_bfloat16 *chi_p, *clo_p, *ahi_p, *alo_p, *xhi_p, *xlo_p;
    cudaGetSymbolAddress((void**)&w_p,  g_w);
    cudaGetSymbolAddress((void**)&p1_p, g_p1);
    cudaGetSymbolAddress((void**)&p3_p, g_p3);
    cudaGetSymbolAddress((void**)&chi_p, g_Chi);
    cudaGetSymbolAddress((void**)&clo_p, g_Clo);
    cudaGetSymbolAddress((void**)&ahi_p, g_Ahi);
    cudaGetSymbolAddress((void**)&alo_p, g_Alo);
    cudaGetSymbolAddress((void**)&xhi_p, g_Xhi);
    cudaGetSymbolAddress((void**)&xlo_p, g_Xlo);

    cudaFuncSetAttribute((const void*)gemm_mma_kernel<64, 4, false, 1024>,
                         cudaFuncAttributeMaxDynamicSharedMemorySize, SMEM64);
    cudaFuncSetAttribute((const void*)gemm_mma_kernel<128, 1, true, 16384>,
                         cudaFuncAttributeMaxDynamicSharedMemorySize, SMEM128);

    // x -> bf16 hi/lo (gemm3 A)
    convert_split_kernel<<<(Bsz * Kd) / 512, 256>>>(x, xhi_p, xlo_p);

    // LN -> cond hi/lo (gemm1 A)
    ln_kernel<<<Bsz, 256>>>(ada, gam, bet);

    // GEMM1 partials: cond @ W1  (split-K=4)
    gemm_mma_kernel<64, 4, false, 1024><<<dim3(16, 2, 4), 256, SMEM64>>>(
        chi_p, clo_p, W1, nullptr, p1_p);

    // GEMM3 partials: x @ base  (split-K=4)
    gemm_mma_kernel<64, 4, false, 1024><<<dim3(16, 2, 4), 256, SMEM64>>>(
        xhi_p, xlo_p, base, nullptr, p3_p);

    // reduce1: + b1, GELU, split -> g_Ahi/g_Alo
    reduce1_kernel<<<(Bsz * Dd) / 1024, 256>>>(b1);

    // GEMM2: w = h @ W2 + b2
    gemm_mma_kernel<128, 1, true, 16384><<<dim3(W2N / 128, Bsz / BM, 1), 256, SMEM128>>>(
        ahi_p, alo_p, W2, b2, w_p);

    // t[b,r]
    t_kernel<<<Bsz, 256>>>(x);

    // final epilogue
    reduce3_kernel<<<dim3(2, Bsz), 256>>>(x, out);
}

// round 6
// speedup vs baseline: 3.3625x; 1.8059x over previous
#include <cuda_runtime.h>
#include <cuda_bf16.h>
#include <math.h>
#include <cstdint>

// ---------------------------------------------------------------------------
// AdaLoRAWithBase restructured:
//   out = x + x@base + sum_r t[b,r] * x_b[b,:,r],  t[b,r] = sum_c x[b,c]*x_a[b,c,r]
//   [x_a|x_b] = GELU(LN(ada)@W1+b1) @ W2 + b2
// All GEMMs on mma.sync bf16 hi/lo 3-pass, fused fp32->bf16 B conversion.
// R6: gemm2 single-wave (BN=256, 512 thr, grid 128); gemm1+gemm3 fused into one
// dual launch (grid 256, 2 CTA/SM); PSTG=3.
// ---------------------------------------------------------------------------

namespace {
constexpr int Bsz = 256;
constexpr int Dd  = 1024;
constexpr int Aa  = 1024;
constexpr int Rr  = 8;
constexpr int W2N = Dd * Rr * 2;     // 16384
constexpr int Kd  = 1024;

constexpr int BM = 128, BK = 32;
constexpr int PSTG = 3;
constexpr int A_ROWB = 80;           // bytes per A smem row (40 bf16)
}

// Scratch (device globals)
__device__ __align__(16) float g_w[(size_t)Bsz * W2N];   // 16 MB
__device__ __align__(16) float g_t[Bsz * Rr];
__device__ __align__(16) float g_p1[4 * Bsz * Dd];
__device__ __align__(16) float g_p3[4 * Bsz * Dd];
__device__ __align__(16) __nv_bfloat16 g_Chi[Bsz * Kd];
__device__ __align__(16) __nv_bfloat16 g_Clo[Bsz * Kd];
__device__ __align__(16) __nv_bfloat16 g_Ahi[Bsz * Kd];
__device__ __align__(16) __nv_bfloat16 g_Alo[Bsz * Kd];
__device__ __align__(16) __nv_bfloat16 g_Xhi[Bsz * Kd];
__device__ __align__(16) __nv_bfloat16 g_Xlo[Bsz * Kd];

// ---------------------------------------------------------------------------
// PTX helpers (baseline sm_80+)
// ---------------------------------------------------------------------------
__device__ __forceinline__ uint32_t smem_u32(const void* p) {
    uint32_t a;
    asm("{ .reg .u64 t; cvta.to.shared.u64 t, %1; cvt.u32.u64 %0, t; }" : "=r"(a) : "l"(p));
    return a;
}
__device__ __forceinline__ void cp_async16(uint32_t saddr, const void* gaddr) {
    asm volatile("cp.async.cg.shared.global [%0], [%1], 16;" :: "r"(saddr), "l"(gaddr) : "memory");
}
__device__ __forceinline__ void cp_commit() {
    asm volatile("cp.async.commit_group;" ::: "memory");
}
template <int N>
__device__ __forceinline__ void cp_wait() {
    asm volatile("cp.async.wait_group %0;" :: "n"(N) : "memory");
}
__device__ __forceinline__ void ldsm_x4(uint32_t& r0, uint32_t& r1, uint32_t& r2, uint32_t& r3,
                                        uint32_t addr) {
    asm volatile("ldmatrix.sync.aligned.m8n8.x4.shared.b16 {%0,%1,%2,%3}, [%4];"
                 : "=r"(r0), "=r"(r1), "=r"(r2), "=r"(r3) : "r"(addr));
}
__device__ __forceinline__ void ldsm_x2_trans(uint32_t& r0, uint32_t& r1, uint32_t addr) {
    asm volatile("ldmatrix.sync.aligned.m8n8.x2.trans.shared.b16 {%0,%1}, [%2];"
                 : "=r"(r0), "=r"(r1) : "r"(addr));
}
__device__ __forceinline__ void mma16816(float* c, uint32_t a0, uint32_t a1, uint32_t a2,
                                         uint32_t a3, uint32_t b0, uint32_t b1) {
    asm volatile(
        "mma.sync.aligned.m16n8k16.row.col.f32.bf16.bf16.f32 "
        "{%0,%1,%2,%3},{%4,%5,%6,%7},{%8,%9},{%0,%1,%2,%3};"
        : "+f"(c[0]), "+f"(c[1]), "+f"(c[2]), "+f"(c[3])
        : "r"(a0), "r"(a1), "r"(a2), "r"(a3), "r"(b0), "r"(b1));
}

// ---------------------------------------------------------------------------
// LayerNorm -> bf16 hi/lo
// ---------------------------------------------------------------------------
__global__ void __launch_bounds__(256) ln_kernel(
    const float* __restrict__ ada, const float* __restrict__ gamma,
    const float* __restrict__ beta)
{
    int b = blockIdx.x;
    const float* row = ada + (size_t)b * Aa;
    float s = 0.f, s2 = 0.f;
    for (int i = threadIdx.x; i < Aa; i += blockDim.x) {
        float v = row[i]; s += v; s2 += v * v;
    }
    #pragma unroll
    for (int o = 16; o; o >>= 1) {
        s  += __shfl_down_sync(0xFFFFFFFFu, s,  o);
        s2 += __shfl_down_sync(0xFFFFFFFFu, s2, o);
    }
    __shared__ float red0[8], red1[8], mv[2];
    int wid = threadIdx.x >> 5, lid = threadIdx.x & 31;
    if (lid == 0) { red0[wid] = s; red1[wid] = s2; }
    __syncthreads();
    if (threadIdx.x == 0) {
        float ts = 0.f, ts2 = 0.f;
        #pragma unroll
        for (int i = 0; i < 8; i++) { ts += red0[i]; ts2 += red1[i]; }
        float mu = ts * (1.f / Aa);
        float var = ts2 * (1.f / Aa) - mu * mu;
        mv[0] = mu; mv[1] = rsqrtf(var + 1e-5f);
    }
    __syncthreads();
    float mu = mv[0], rs = mv[1];
    for (int i = threadIdx.x; i < Aa; i += blockDim.x) {
        float v = (row[i] - mu) * rs * gamma[i] + beta[i];
        __nv_bfloat16 hi = __float2bfloat16(v);
        g_Chi[(size_t)b * Aa + i] = hi;
        g_Clo[(size_t)b * Aa + i] = __float2bfloat16(v - __bfloat162float(hi));
    }
}

// ---------------------------------------------------------------------------
// fp32 -> bf16 hi/lo (for x)
// ---------------------------------------------------------------------------
__global__ void __launch_bounds__(256) convert_split_kernel(
    const float* __restrict__ src, __nv_bfloat16* __restrict__ hi,
    __nv_bfloat16* __restrict__ lo)
{
    int i = (blockIdx.x * 256 + threadIdx.x) * 2;
    float v0 = src[i], v1 = src[i + 1];
    __nv_bfloat16 h0 = __float2bfloat16(v0), h1 = __float2bfloat16(v1);
    float l0 = v0 - __bfloat162float(h0), l1 = v1 - __bfloat162float(h1);
    *reinterpret_cast<__nv_bfloat162*>(&hi[i]) = __halves2bfloat162(h0, h1);
    *reinterpret_cast<__nv_bfloat162*>(&lo[i]) =
        __halves2bfloat162(__float2bfloat16(l0), __float2bfloat16(l1));
}

// ---------------------------------------------------------------------------
// t[b,r] = sum_d x[b,d] * g_w[b, d*R + r]
// ---------------------------------------------------------------------------
__global__ void __launch_bounds__(256) t_kernel(const float* __restrict__ x)
{
    int b = blockIdx.x;
    const float* wrow = g_w + (size_t)b * W2N;
    const float* xrow = x + (size_t)b * Dd;
    float acc[Rr] = {};
    for (int d = threadIdx.x; d < Dd; d += blockDim.x) {
        float xv = xrow[d];
        float4 w0 = *reinterpret_cast<const float4*>(wrow + (size_t)d * Rr);
        float4 w1 = *reinterpret_cast<const float4*>(wrow + (size_t)d * Rr + 4);
        acc[0] += xv*w0.x; acc[1] += xv*w0.y; acc[2] += xv*w0.z; acc[3] += xv*w0.w;
        acc[4] += xv*w1.x; acc[5] += xv*w1.y; acc[6] += xv*w1.z; acc[7] += xv*w1.w;
    }
    #pragma unroll
    for (int o = 16; o; o >>= 1)
        #pragma unroll
        for (int r = 0; r < Rr; r++)
            acc[r] += __shfl_down_sync(0xFFFFFFFFu, acc[r], o);
    __shared__ float red[Rr][8];
    int wid = threadIdx.x >> 5, lid = threadIdx.x & 31;
    if (lid == 0)
        #pragma unroll
        for (int r = 0; r < Rr; r++) red[r][wid] = acc[r];
    __syncthreads();
    if (threadIdx.x < Rr) {
        int r = threadIdx.x;
        float s = 0.f;
        #pragma unroll
        for (int w = 0; w < 8; w++) s += red[r][w];
        g_t[(size_t)b * Rr + r] = s;
    }
}

// ---------------------------------------------------------------------------
// Unified bf16 hi/lo 3-pass MMA GEMM, fused fp32 B conversion, PSTG=3.
// NWM x NWN warps; warp tile (BM/NWM) x (BN_/NWN); BM=128 fixed -> NWM in {2}.
// DUAL: blockIdx.z selects problem 0 (z<SK) or 1 (z>=SK), same shape.
// ---------------------------------------------------------------------------
template <int BN_, int N_, int NTHR>
__device__ __forceinline__ void load_grp(
    uint32_t sstage, const __nv_bfloat16* __restrict__ ahi,
    const __nv_bfloat16* __restrict__ alo, const float* __restrict__ Braw,
    int m0, int n0, int k0, int tid)
{
    constexpr int RCHR = BN_ / 4;
    constexpr int TOT = 1024 + 8 * BN_;
    #pragma unroll
    for (int it = 0; it < TOT / NTHR; it++) {
        int idx = tid + it * NTHR;
        if (idx < 512) {
            int row = idx >> 2, ch = idx & 3;
            cp_async16(sstage + row * A_ROWB + ch * 16,
                       &ahi[(size_t)(m0 + row) * Kd + k0 + ch * 8]);
        } else if (idx < 1024) {
            int l = idx - 512, row = l >> 2, ch = l & 3;
            cp_async16(sstage + 10240 + row * A_ROWB + ch * 16,
                       &alo[(size_t)(m0 + row) * Kd + k0 + ch * 8]);
        } else {
            int l = idx - 1024;
            int row = l / RCHR, ch = l % RCHR;
            cp_async16(sstage + 20480 + row * (BN_ * 4) + ch * 16,
                       &Braw[(size_t)(k0 + row) * N_ + n0 + ch * 4]);
        }
    }
    cp_commit();
}

template <int BN_, int NTHR>
__device__ __forceinline__ void conv_b(char* smem, uint32_t raw_off, uint32_t bb_off,
                                       uint32_t bb_half, int tid)
{
    constexpr int B_RL = BN_ + 8;
    constexpr int RC = 8 * BN_;
    #pragma unroll
    for (int i = 0; i < RC / NTHR; i++) {
        int c = tid + i * NTHR;
        float4 v = *reinterpret_cast<const float4*>(smem + raw_off + c * 16);
        int row = c / (BN_ / 4);
        int col = (c % (BN_ / 4)) * 4;
        __nv_bfloat16 h0 = __float2bfloat16(v.x), h1 = __float2bfloat16(v.y);
        __nv_bfloat16 h2 = __float2bfloat16(v.z), h3 = __float2bfloat16(v.w);
        float l0 = v.x - __bfloat162float(h0), l1 = v.y - __bfloat162float(h1);
        float l2 = v.z - __bfloat162float(h2), l3 = v.w - __bfloat162float(h3);
        uint32_t eoff = (uint32_t)(row * B_RL + col) * 2;
        char* hi = smem + bb_off + eoff;
        char* lo = smem + bb_off + bb_half + eoff;
        *reinterpret_cast<__nv_bfloat162*>(hi)     = __halves2bfloat162(h0, h1);
        *reinterpret_cast<__nv_bfloat162*>(hi + 4) = __halves2bfloat162(h2, h3);
        *reinterpret_cast<__nv_bfloat162*>(lo)     =
            __halves2bfloat162(__float2bfloat16(l0), __float2bfloat16(l1));
        *reinterpret_cast<__nv_bfloat162*>(lo + 4) =
            __halves2bfloat162(__float2bfloat16(l2), __float2bfloat16(l3));
    }
}

template <int BN_, int SK, bool HAS_BIAS, int N_, int NWM, int NWN, bool DUAL, int MINB>
__global__ void __launch_bounds__(NWM * NWN * 32, MINB) gemm_mma_kernel(
    const __nv_bfloat16* __restrict__ ahi0, const __nv_bfloat16* __restrict__ alo0,
    const float* __restrict__ Braw0, float* __restrict__ C0,
    const __nv_bfloat16* __restrict__ ahi1, const __nv_bfloat16* __restrict__ alo1,
    const float* __restrict__ Braw1, float* __restrict__ C1,
    const float* __restrict__ bias)
{
    constexpr int NTHR = NWM * NWN * 32;
    constexpr int WN   = BN_ / NWN;          // per-warp n width
    constexpr int NT   = WN / 8;
    constexpr int B_RL = BN_ + 8;
    constexpr int STG  = 20480 + 128 * BN_;
    constexpr int OFF_BBc = PSTG * STG;
    constexpr int BB_HALFc = 32 * B_RL * 2;
    constexpr int BB_SZc = 2 * BB_HALFc;
    constexpr int KITERS = Kd / SK / BK;

    extern __shared__ char smem[];
    uint32_t sb = smem_u32(smem);
    const int tid = threadIdx.x, lane = tid & 31, wid = tid >> 5;
    const int warp_m = wid / NWN, warp_n = wid % NWN;
    const int m0 = blockIdx.y * BM, n0 = blockIdx.x * BN_;

    int z = blockIdx.z;
    const __nv_bfloat16* ahi = ahi0;
    const __nv_bfloat16* alo = alo0;
    const float* Braw = Braw0;
    float* C = C0;
    if (DUAL && z >= SK) {
        z -= SK; ahi = ahi1; alo = alo1; Braw = Braw1; C = C1;
    }
    const int kb = z * (Kd / SK);

    float acc[4][NT][4];
    #pragma unroll
    for (int i = 0; i < 4; i++)
        #pragma unroll
        for (int j = 0; j < NT; j++)
            #pragma unroll
            for (int r = 0; r < 4; r++) acc[i][j][r] = 0.f;

    float2 biasv[NT];
    if constexpr (HAS_BIAS) {
        #pragma unroll
        for (int nt = 0; nt < NT; nt++)
            biasv[nt] = *reinterpret_cast<const float2*>(
                &bias[n0 + warp_n * WN + nt * 8 + (lane & 3) * 2]);
    }

    // prologue: 2 stages
    load_grp<BN_, N_, NTHR>(sb, ahi, alo, Braw, m0, n0, kb, tid);
    load_grp<BN_, N_, NTHR>(sb + STG, ahi, alo, Braw, m0, n0, kb + BK, tid);

    cp_wait<1>();    // S0 arrived (raw chunks are self-written: no barrier needed)
    conv_b<BN_, NTHR>(smem, 20480, OFF_BBc, BB_HALFc, tid);

    const int a_row_in_tile = lane & 15;
    const int a_colblk = (lane >> 4) << 3;
    const int b_row_in_tile = (lane & 7) + ((lane >> 3) & 1) * 8;
    const int b_ncol = warp_n * WN;

    for (int kt = 0; kt < KITERS; kt++) {
        cp_wait<0>();          // stage kt+1 arrived
        __syncthreads();       // bb[kt&1] conv + prior reads visible/done

        if (kt + 2 < KITERS)
            load_grp<BN_, N_, NTHR>(sb + ((kt + 2) % PSTG) * STG, ahi, alo, Braw,
                                    m0, n0, kb + (kt + 2) * BK, tid);
        if (kt + 1 < KITERS)
            conv_b<BN_, NTHR>(smem, ((kt + 1) % PSTG) * STG + 20480,
                              OFF_BBc + ((kt + 1) & 1) * BB_SZc, BB_HALFc, tid);

        uint32_t abase = sb + (kt % PSTG) * STG;
        uint32_t bbase = sb + OFF_BBc + (kt & 1) * BB_SZc;

        #pragma unroll
        for (int ks = 0; ks < 2; ks++) {
            uint32_t af[4][4], bf[NT][2], bl2[NT][2];
            #pragma unroll
            for (int mt = 0; mt < 4; mt++) {
                int row = warp_m * 64 + mt * 16 + a_row_in_tile;
                uint32_t off = (uint32_t)(row * 40 + ks * 16 + a_colblk) * 2;
                ldsm_x4(af[mt][0], af[mt][1], af[mt][2], af[mt][3], abase + off);
            }
            #pragma unroll
            for (int nt = 0; nt < NT; nt++) {
                int krow = ks * 16 + b_row_in_tile;
                uint32_t off = (uint32_t)(krow * B_RL + b_ncol + nt * 8) * 2;
                ldsm_x2_trans(bf[nt][0], bf[nt][1], bbase + off);
            }
            // pass 1: hi*hi
            #pragma unroll
            for (int mt = 0; mt < 4; mt++)
                #pragma unroll
                for (int nt = 0; nt < NT; nt++)
                    mma16816(acc[mt][nt], af[mt][0], af[mt][1], af[mt][2], af[mt][3],
                             bf[nt][0], bf[nt][1]);
            #pragma unroll
            for (int nt = 0; nt < NT; nt++) {
                int krow = ks * 16 + b_row_in_tile;
                uint32_t off = (uint32_t)(krow * B_RL + b_ncol + nt * 8) * 2;
                ldsm_x2_trans(bl2[nt][0], bl2[nt][1], bbase + BB_HALFc + off);
            }
            // pass 2: hi*lo
            #pragma unroll
            for (int mt = 0; mt < 4; mt++)
                #pragma unroll
                for (int nt = 0; nt < NT; nt++)
                    mma16816(acc[mt][nt], af[mt][0], af[mt][1], af[mt][2], af[mt][3],
                             bl2[nt][0], bl2[nt][1]);
            // reload A-lo into af (A-hi dead)
            #pragma unroll
            for (int mt = 0; mt < 4; mt++) {
                int row = warp_m * 64 + mt * 16 + a_row_in_tile;
                uint32_t off = (uint32_t)(row * 40 + ks * 16 + a_colblk) * 2;
                ldsm_x4(af[mt][0], af[mt][1], af[mt][2], af[mt][3], abase + 10240 + off);
            }
            // pass 3: lo*hi
            #pragma unroll
            for (int mt = 0; mt < 4; mt++)
                #pragma unroll
                for (int nt = 0; nt < NT; nt++)
                    mma16816(acc[mt][nt], af[mt][0], af[mt][1], af[mt][2], af[mt][3],
                             bf[nt][0], bf[nt][1]);
        }
    }

    float* Cw = C + (size_t)z * Bsz * N_ * (SK > 1 ? 1 : 0);
    if constexpr (SK == 1) Cw = C;
    #pragma unroll
    for (int mt = 0; mt < 4; mt++) {
        int row0 = m0 + warp_m * 64 + mt * 16 + (lane >> 2);
        #pragma unroll
        for (int nt = 0; nt < NT; nt++) {
            int col = n0 + warp_n * WN + nt * 8 + (lane & 3) * 2;
            float bx = 0.f, by = 0.f;
            if constexpr (HAS_BIAS) { bx = biasv[nt].x; by = biasv[nt].y; }
            float2 v0 = make_float2(acc[mt][nt][0] + bx, acc[mt][nt][1] + by);
            float2 v1 = make_float2(acc[mt][nt][2] + bx, acc[mt][nt][3] + by);
            *reinterpret_cast<float2*>(&Cw[(size_t)row0 * N_ + col]) = v0;
            *reinterpret_cast<float2*>(&Cw[(size_t)(row0 + 8) * N_ + col]) = v1;
        }
    }
}

// ---------------------------------------------------------------------------
// reduce1: h = GELU(sum_z p1[z] + b1) -> bf16 hi/lo
// ---------------------------------------------------------------------------
__global__ void __launch_bounds__(256) reduce1_kernel(const float* __restrict__ b1)
{
    int e = (blockIdx.x * 256 + threadIdx.x) * 4;
    float4 s = *reinterpret_cast<const float4*>(&g_p1[e]);
    #pragma unroll
    for (int z = 1; z < 4; z++) {
        float4 p = *reinterpret_cast<const float4*>(&g_p1[z * (Bsz * Dd) + e]);
        s.x += p.x; s.y += p.y; s.z += p.z; s.w += p.w;
    }
    float4 bb = *reinterpret_cast<const float4*>(&b1[e & (Dd - 1)]);
    float u[4] = {s.x + bb.x, s.y + bb.y, s.z + bb.z, s.w + bb.w};
    __nv_bfloat16 hi[4], lo[4];
    #pragma unroll
    for (int i = 0; i < 4; i++) {
        float g = 0.5f * u[i] * (1.f + erff(u[i] * 0.70710678118654752f));
        hi[i] = __float2bfloat16(g);
        lo[i] = __float2bfloat16(g - __bfloat162float(hi[i]));
    }
    *reinterpret_cast<__nv_bfloat162*>(&g_Ahi[e])     = __halves2bfloat162(hi[0], hi[1]);
    *reinterpret_cast<__nv_bfloat162*>(&g_Ahi[e + 2]) = __halves2bfloat162(hi[2], hi[3]);
    *reinterpret_cast<__nv_bfloat162*>(&g_Alo[e])     = __halves2bfloat162(lo[0], lo[1]);
    *reinterpret_cast<__nv_bfloat162*>(&g_Alo[e + 2]) = __halves2bfloat162(lo[2], lo[3]);
}

// ---------------------------------------------------------------------------
// reduce3: out = x + sum_z p3[z] + rank-8 epilogue
// ---------------------------------------------------------------------------
__global__ void __launch_bounds__(256) reduce3_kernel(
    const float* __restrict__ x, float* __restrict__ out)
{
    int b = blockIdx.y;
    int o = blockIdx.x * 512 + threadIdx.x * 2;
    size_t e = (size_t)b * Dd + o;
    float2 s = *reinterpret_cast<const float2*>(&x[e]);
    #pragma unroll
    for (int z = 0; z < 4; z++) {
        float2 p = *reinterpret_cast<const float2*>(&g_p3[z * (Bsz * Dd) + e]);
        s.x += p.x; s.y += p.y;
    }
    const float* tr = &g_t[b * Rr];
    float t0 = tr[0], t1 = tr[1], t2 = tr[2], t3 = tr[3];
    float t4 = tr[4], t5 = tr[5], t6 = tr[6], t7 = tr[7];
    const float* wb = &g_w[(size_t)b * W2N + (size_t)Dd * Rr + (size_t)o * Rr];
    float4 w0 = *reinterpret_cast<const float4*>(wb);
    float4 w1 = *reinterpret_cast<const float4*>(wb + 4);
    float4 w2 = *reinterpret_cast<const float4*>(wb + 8);
    float4 w3 = *reinterpret_cast<const float4*>(wb + 12);
    float lr0 = t0*w0.x + t1*w0.y + t2*w0.z + t3*w0.w
              + t4*w1.x + t5*w1.y + t6*w1.z + t7*w1.w;
    float lr1 = t0*w2.x + t1*w2.y + t2*w2.z + t3*w2.w
              + t4*w3.x + t5*w3.y + t6*w3.z + t7*w3.w;
    *reinterpret_cast<float2*>(&out[e]) = make_float2(s.x + lr0, s.y + lr1);
}

// ---------------------------------------------------------------------------
extern "C" void kernel_launch(void* const* d_in, const int* in_sizes, int n_in,
                              void* d_out, int out_size)
{
    const float* x    = (const float*)d_in[0];
    const float* ada  = (const float*)d_in[1];
    const float* base = (const float*)d_in[2];
    const float* gam  = (const float*)d_in[3];
    const float* bet  = (const float*)d_in[4];
    const float* W1   = (const float*)d_in[5];
    const float* b1   = (const float*)d_in[6];
    const float* W2   = (const float*)d_in[7];
    const float* b2   = (const float*)d_in[8];
    float* out = (float*)d_out;

    // smem: STG = 20480 + 128*BN; total = 3*STG + 2*(2*32*(BN+8)*2)
    constexpr int SMEM64  = 3 * (20480 + 128 * 64)  + 2 * (2 * 32 * 72 * 2);   // 104448
    constexpr int SMEM256 = 3 * (20480 + 128 * 256) + 2 * (2 * 32 * 264 * 2);  // 227328

    float *w_p, *p1_p, *p3_p;
    __nv_bfloat16 *chi_p, *clo_p, *ahi_p, *alo_p, *xhi_p, *xlo_p;
    cudaGetSymbolAddress((void**)&w_p,  g_w);
    cudaGetSymbolAddress((void**)&p1_p, g_p1);
    cudaGetSymbolAddress((void**)&p3_p, g_p3);
    cudaGetSymbolAddress((void**)&chi_p, g_Chi);
    cudaGetSymbolAddress((void**)&clo_p, g_Clo);
    cudaGetSymbolAddress((void**)&ahi_p, g_Ahi);
    cudaGetSymbolAddress((void**)&alo_p, g_Alo);
    cudaGetSymbolAddress((void**)&xhi_p, g_Xhi);
    cudaGetSymbolAddress((void**)&xlo_p, g_Xlo);

    // gemm13: BN=64, SK=4, no bias, N=1024, 2x4 warps (256 thr), DUAL, 2 blocks/SM
    auto k13 = gemm_mma_kernel<64, 4, false, 1024, 2, 4, true, 2>;
    // gemm2: BN=256, SK=1, bias, N=16384, 2x8 warps (512 thr), single
    auto k2  = gemm_mma_kernel<256, 1, true, 16384, 2, 8, false, 1>;

    cudaFuncSetAttribute((const void*)k13,
                         cudaFuncAttributeMaxDynamicSharedMemorySize, SMEM64);
    cudaFuncSetAttribute((const void*)k2,
                         cudaFuncAttributeMaxDynamicSharedMemorySize, SMEM256);

    // x -> bf16 hi/lo (gemm3 A)
    convert_split_kernel<<<(Bsz * Kd) / 512, 256>>>(x, xhi_p, xlo_p);

    // LN -> cond hi/lo (gemm1 A)
    ln_kernel<<<Bsz, 256>>>(ada, gam, bet);

    // GEMM1 + GEMM3 fused launch: z<4 -> cond@W1 partials, z>=4 -> x@base partials
    k13<<<dim3(16, 2, 8), 256, SMEM64>>>(
        chi_p, clo_p, W1, p1_p,
        xhi_p, xlo_p, base, p3_p, nullptr);

    // reduce1: + b1, GELU, split -> g_Ahi/g_Alo
    reduce1_kernel<<<(Bsz * Dd) / 1024, 256>>>(b1);

    // GEMM2: w = h @ W2 + b2  (single wave, 128 CTAs, 512 threads)
    k2<<<dim3(W2N / 256, Bsz / BM, 1), 512, SMEM256>>>(
        ahi_p, alo_p, W2, w_p,
        nullptr, nullptr, nullptr, nullptr, b2);

    // t[b,r]
    t_kernel<<<Bsz, 256>>>(x);

    // final epilogue
    reduce3_kernel<<<dim3(2, Bsz), 256>>>(x, out);
}

// round 7
// speedup vs baseline: 3.4286x; 1.0197x over previous
#include <cuda_runtime.h>
#include <cuda_bf16.h>
#include <math.h>
#include <cstdint>

// ---------------------------------------------------------------------------
// AdaLoRAWithBase restructured:
//   out = x + x@base + sum_r t[b,r] * x_b[b,:,r],  t[b,r] = sum_c x[b,c]*x_a[b,c,r]
//   [x_a|x_b] = GELU(LN(ada)@W1+b1) @ W2 + b2
// All GEMMs on mma.sync bf16 hi/lo 3-pass, fused fp32->bf16 B conversion.
// R7: t[b,r] fused into gemm2 epilogue (x_a half never hits gmem);
//     convert+ln merged; g_w holds x_b only.
// ---------------------------------------------------------------------------

namespace {
constexpr int Bsz = 256;
constexpr int Dd  = 1024;
constexpr int Aa  = 1024;
constexpr int Rr  = 8;
constexpr int W2N = Dd * Rr * 2;     // 16384
constexpr int XBN = Dd * Rr;         // 8192 (x_b width)
constexpr int Kd  = 1024;

constexpr int BM = 128, BK = 32;
constexpr int PSTG = 3;
constexpr int A_ROWB = 80;           // bytes per A smem row (40 bf16)
}

// Scratch (device globals)
__device__ __align__(16) float g_w[(size_t)Bsz * XBN];   // 8 MB (x_b only)
__device__ __align__(16) float g_tp[32 * Bsz * Rr];      // per-CTA t partials
__device__ __align__(16) float g_p1[4 * Bsz * Dd];
__device__ __align__(16) float g_p3[4 * Bsz * Dd];
__device__ __align__(16) __nv_bfloat16 g_Chi[Bsz * Kd];
__device__ __align__(16) __nv_bfloat16 g_Clo[Bsz * Kd];
__device__ __align__(16) __nv_bfloat16 g_Ahi[Bsz * Kd];
__device__ __align__(16) __nv_bfloat16 g_Alo[Bsz * Kd];
__device__ __align__(16) __nv_bfloat16 g_Xhi[Bsz * Kd];
__device__ __align__(16) __nv_bfloat16 g_Xlo[Bsz * Kd];

// ---------------------------------------------------------------------------
// PTX helpers (baseline sm_80+)
// ---------------------------------------------------------------------------
__device__ __forceinline__ uint32_t smem_u32(const void* p) {
    uint32_t a;
    asm("{ .reg .u64 t; cvta.to.shared.u64 t, %1; cvt.u32.u64 %0, t; }" : "=r"(a) : "l"(p));
    return a;
}
__device__ __forceinline__ void cp_async16(uint32_t saddr, const void* gaddr) {
    asm volatile("cp.async.cg.shared.global [%0], [%1], 16;" :: "r"(saddr), "l"(gaddr) : "memory");
}
__device__ __forceinline__ void cp_commit() {
    asm volatile("cp.async.commit_group;" ::: "memory");
}
template <int N>
__device__ __forceinline__ void cp_wait() {
    asm volatile("cp.async.wait_group %0;" :: "n"(N) : "memory");
}
__device__ __forceinline__ void ldsm_x4(uint32_t& r0, uint32_t& r1, uint32_t& r2, uint32_t& r3,
                                        uint32_t addr) {
    asm volatile("ldmatrix.sync.aligned.m8n8.x4.shared.b16 {%0,%1,%2,%3}, [%4];"
                 : "=r"(r0), "=r"(r1), "=r"(r2), "=r"(r3) : "r"(addr));
}
__device__ __forceinline__ void ldsm_x2_trans(uint32_t& r0, uint32_t& r1, uint32_t addr) {
    asm volatile("ldmatrix.sync.aligned.m8n8.x2.trans.shared.b16 {%0,%1}, [%2];"
                 : "=r"(r0), "=r"(r1) : "r"(addr));
}
__device__ __forceinline__ void mma16816(float* c, uint32_t a0, uint32_t a1, uint32_t a2,
                                         uint32_t a3, uint32_t b0, uint32_t b1) {
    asm volatile(
        "mma.sync.aligned.m16n8k16.row.col.f32.bf16.bf16.f32 "
        "{%0,%1,%2,%3},{%4,%5,%6,%7},{%8,%9},{%0,%1,%2,%3};"
        : "+f"(c[0]), "+f"(c[1]), "+f"(c[2]), "+f"(c[3])
        : "r"(a0), "r"(a1), "r"(a2), "r"(a3), "r"(b0), "r"(b1));
}

// ---------------------------------------------------------------------------
// Merged pre-pass: blocks [0,256) do LayerNorm rows; blocks [256,768) split x.
// ---------------------------------------------------------------------------
__global__ void __launch_bounds__(256) prepass_kernel(
    const float* __restrict__ ada, const float* __restrict__ gamma,
    const float* __restrict__ beta, const float* __restrict__ x)
{
    if (blockIdx.x < 256) {
        int b = blockIdx.x;
        const float* row = ada + (size_t)b * Aa;
        float s = 0.f, s2 = 0.f;
        for (int i = threadIdx.x; i < Aa; i += blockDim.x) {
            float v = row[i]; s += v; s2 += v * v;
        }
        #pragma unroll
        for (int o = 16; o; o >>= 1) {
            s  += __shfl_down_sync(0xFFFFFFFFu, s,  o);
            s2 += __shfl_down_sync(0xFFFFFFFFu, s2, o);
        }
        __shared__ float red0[8], red1[8], mv[2];
        int wid = threadIdx.x >> 5, lid = threadIdx.x & 31;
        if (lid == 0) { red0[wid] = s; red1[wid] = s2; }
        __syncthreads();
        if (threadIdx.x == 0) {
            float ts = 0.f, ts2 = 0.f;
            #pragma unroll
            for (int i = 0; i < 8; i++) { ts += red0[i]; ts2 += red1[i]; }
            float mu = ts * (1.f / Aa);
            float var = ts2 * (1.f / Aa) - mu * mu;
            mv[0] = mu; mv[1] = rsqrtf(var + 1e-5f);
        }
        __syncthreads();
        float mu = mv[0], rs = mv[1];
        for (int i = threadIdx.x; i < Aa; i += blockDim.x) {
            float v = (row[i] - mu) * rs * gamma[i] + beta[i];
            __nv_bfloat16 hi = __float2bfloat16(v);
            g_Chi[(size_t)b * Aa + i] = hi;
            g_Clo[(size_t)b * Aa + i] = __float2bfloat16(v - __bfloat162float(hi));
        }
    } else {
        int i = ((blockIdx.x - 256) * 256 + threadIdx.x) * 2;
        float v0 = x[i], v1 = x[i + 1];
        __nv_bfloat16 h0 = __float2bfloat16(v0), h1 = __float2bfloat16(v1);
        float l0 = v0 - __bfloat162float(h0), l1 = v1 - __bfloat162float(h1);
        *reinterpret_cast<__nv_bfloat162*>(&g_Xhi[i]) = __halves2bfloat162(h0, h1);
        *reinterpret_cast<__nv_bfloat162*>(&g_Xlo[i]) =
            __halves2bfloat162(__float2bfloat16(l0), __float2bfloat16(l1));
    }
}

// ---------------------------------------------------------------------------
// Unified bf16 hi/lo 3-pass MMA GEMM, fused fp32 B conversion, PSTG=3.
// FUSE_T: x_a-half CTAs (blockIdx.x < 32) compute t partials instead of storing.
// ---------------------------------------------------------------------------
template <int BN_, int N_, int NTHR>
__device__ __forceinline__ void load_grp(
    uint32_t sstage, const __nv_bfloat16* __restrict__ ahi,
    const __nv_bfloat16* __restrict__ alo, const float* __restrict__ Braw,
    int m0, int n0, int k0, int tid)
{
    constexpr int RCHR = BN_ / 4;
    constexpr int TOT = 1024 + 8 * BN_;
    #pragma unroll
    for (int it = 0; it < TOT / NTHR; it++) {
        int idx = tid + it * NTHR;
        if (idx < 512) {
            int row = idx >> 2, ch = idx & 3;
            cp_async16(sstage + row * A_ROWB + ch * 16,
                       &ahi[(size_t)(m0 + row) * Kd + k0 + ch * 8]);
        } else if (idx < 1024) {
            int l = idx - 512, row = l >> 2, ch = l & 3;
            cp_async16(sstage + 10240 + row * A_ROWB + ch * 16,
                       &alo[(size_t)(m0 + row) * Kd + k0 + ch * 8]);
        } else {
            int l = idx - 1024;
            int row = l / RCHR, ch = l % RCHR;
            cp_async16(sstage + 20480 + row * (BN_ * 4) + ch * 16,
                       &Braw[(size_t)(k0 + row) * N_ + n0 + ch * 4]);
        }
    }
    cp_commit();
}

template <int BN_, int NTHR>
__device__ __forceinline__ void conv_b(char* smem, uint32_t raw_off, uint32_t bb_off,
                                       uint32_t bb_half, int tid)
{
    constexpr int B_RL = BN_ + 8;
    constexpr int RC = 8 * BN_;
    #pragma unroll
    for (int i = 0; i < RC / NTHR; i++) {
        int c = tid + i * NTHR;
        float4 v = *reinterpret_cast<const float4*>(smem + raw_off + c * 16);
        int row = c / (BN_ / 4);
        int col = (c % (BN_ / 4)) * 4;
        __nv_bfloat16 h0 = __float2bfloat16(v.x), h1 = __float2bfloat16(v.y);
        __nv_bfloat16 h2 = __float2bfloat16(v.z), h3 = __float2bfloat16(v.w);
        float l0 = v.x - __bfloat162float(h0), l1 = v.y - __bfloat162float(h1);
        float l2 = v.z - __bfloat162float(h2), l3 = v.w - __bfloat162float(h3);
        uint32_t eoff = (uint32_t)(row * B_RL + col) * 2;
        char* hi = smem + bb_off + eoff;
        char* lo = smem + bb_off + bb_half + eoff;
        *reinterpret_cast<__nv_bfloat162*>(hi)     = __halves2bfloat162(h0, h1);
        *reinterpret_cast<__nv_bfloat162*>(hi + 4) = __halves2bfloat162(h2, h3);
        *reinterpret_cast<__nv_bfloat162*>(lo)     =
            __halves2bfloat162(__float2bfloat16(l0), __float2bfloat16(l1));
        *reinterpret_cast<__nv_bfloat162*>(lo + 4) =
            __halves2bfloat162(__float2bfloat16(l2), __float2bfloat16(l3));
    }
}

template <int BN_, int SK, bool HAS_BIAS, int N_, int NWM, int NWN, bool DUAL,
          int MINB, bool FUSE_T>
__global__ void __launch_bounds__(NWM * NWN * 32, MINB) gemm_mma_kernel(
    const __nv_bfloat16* __restrict__ ahi0, const __nv_bfloat16* __restrict__ alo0,
    const float* __restrict__ Braw0, float* __restrict__ C0,
    const __nv_bfloat16* __restrict__ ahi1, const __nv_bfloat16* __restrict__ alo1,
    const float* __restrict__ Braw1, float* __restrict__ C1,
    const float* __restrict__ bias, const float* __restrict__ xsrc)
{
    constexpr int NTHR = NWM * NWN * 32;
    constexpr int WN   = BN_ / NWN;
    constexpr int NT   = WN / 8;
    constexpr int B_RL = BN_ + 8;
    constexpr int STG  = 20480 + 128 * BN_;
    constexpr int OFF_BBc = PSTG * STG;
    constexpr int BB_HALFc = 32 * B_RL * 2;
    constexpr int BB_SZc = 2 * BB_HALFc;
    constexpr int KITERS = Kd / SK / BK;

    extern __shared__ char smem[];
    uint32_t sb = smem_u32(smem);
    const int tid = threadIdx.x, lane = tid & 31, wid = tid >> 5;
    const int warp_m = wid / NWN, warp_n = wid % NWN;
    const int m0 = blockIdx.y * BM, n0 = blockIdx.x * BN_;

    int z = blockIdx.z;
    const __nv_bfloat16* ahi = ahi0;
    const __nv_bfloat16* alo = alo0;
    const float* Braw = Braw0;
    float* C = C0;
    if (DUAL && z >= SK) {
        z -= SK; ahi = ahi1; alo = alo1; Braw = Braw1; C = C1;
    }
    const int kb = z * (Kd / SK);

    float acc[4][NT][4];
    #pragma unroll
    for (int i = 0; i < 4; i++)
        #pragma unroll
        for (int j = 0; j < NT; j++)
            #pragma unroll
            for (int r = 0; r < 4; r++) acc[i][j][r] = 0.f;

    float2 biasv[NT];
    if constexpr (HAS_BIAS) {
        #pragma unroll
        for (int nt = 0; nt < NT; nt++)
            biasv[nt] = *reinterpret_cast<const float2*>(
                &bias[n0 + warp_n * WN + nt * 8 + (lane & 3) * 2]);
    }

    load_grp<BN_, N_, NTHR>(sb, ahi, alo, Braw, m0, n0, kb, tid);
    load_grp<BN_, N_, NTHR>(sb + STG, ahi, alo, Braw, m0, n0, kb + BK, tid);

    cp_wait<1>();
    conv_b<BN_, NTHR>(smem, 20480, OFF_BBc, BB_HALFc, tid);

    const int a_row_in_tile = lane & 15;
    const int a_colblk = (lane >> 4) << 3;
    const int b_row_in_tile = (lane & 7) + ((lane >> 3) & 1) * 8;
    const int b_ncol = warp_n * WN;

    for (int kt = 0; kt < KITERS; kt++) {
        cp_wait<0>();
        __syncthreads();

        if (kt + 2 < KITERS)
            load_grp<BN_, N_, NTHR>(sb + ((kt + 2) % PSTG) * STG, ahi, alo, Braw,
                                    m0, n0, kb + (kt + 2) * BK, tid);
        if (kt + 1 < KITERS)
            conv_b<BN_, NTHR>(smem, ((kt + 1) % PSTG) * STG + 20480,
                              OFF_BBc + ((kt + 1) & 1) * BB_SZc, BB_HALFc, tid);

        uint32_t abase = sb + (kt % PSTG) * STG;
        uint32_t bbase = sb + OFF_BBc + (kt & 1) * BB_SZc;

        #pragma unroll
        for (int ks = 0; ks < 2; ks++) {
            uint32_t af[4][4], bf[NT][2], bl2[NT][2];
            #pragma unroll
            for (int mt = 0; mt < 4; mt++) {
                int row = warp_m * 64 + mt * 16 + a_row_in_tile;
                uint32_t off = (uint32_t)(row * 40 + ks * 16 + a_colblk) * 2;
                ldsm_x4(af[mt][0], af[mt][1], af[mt][2], af[mt][3], abase + off);
            }
            #pragma unroll
            for (int nt = 0; nt < NT; nt++) {
                int krow = ks * 16 + b_row_in_tile;
                uint32_t off = (uint32_t)(krow * B_RL + b_ncol + nt * 8) * 2;
                ldsm_x2_trans(bf[nt][0], bf[nt][1], bbase + off);
            }
            #pragma unroll
            for (int mt = 0; mt < 4; mt++)
                #pragma unroll
                for (int nt = 0; nt < NT; nt++)
                    mma16816(acc[mt][nt], af[mt][0], af[mt][1], af[mt][2], af[mt][3],
                             bf[nt][0], bf[nt][1]);
            #pragma unroll
            for (int nt = 0; nt < NT; nt++) {
                int krow = ks * 16 + b_row_in_tile;
                uint32_t off = (uint32_t)(krow * B_RL + b_ncol + nt * 8) * 2;
                ldsm_x2_trans(bl2[nt][0], bl2[nt][1], bbase + BB_HALFc + off);
            }
            #pragma unroll
            for (int mt = 0; mt < 4; mt++)
                #pragma unroll
                for (int nt = 0; nt < NT; nt++)
                    mma16816(acc[mt][nt], af[mt][0], af[mt][1], af[mt][2], af[mt][3],
                             bl2[nt][0], bl2[nt][1]);
            #pragma unroll
            for (int mt = 0; mt < 4; mt++) {
                int row = warp_m * 64 + mt * 16 + a_row_in_tile;
                uint32_t off = (uint32_t)(row * 40 + ks * 16 + a_colblk) * 2;
                ldsm_x4(af[mt][0], af[mt][1], af[mt][2], af[mt][3], abase + 10240 + off);
            }
            #pragma unroll
            for (int mt = 0; mt < 4; mt++)
                #pragma unroll
                for (int nt = 0; nt < NT; nt++)
                    mma16816(acc[mt][nt], af[mt][0], af[mt][1], af[mt][2], af[mt][3],
                             bf[nt][0], bf[nt][1]);
        }
    }

    if (FUSE_T && blockIdx.x < (XBN / BN_)) {
        // ---- x_a half: t partials. Each nt fragment = one d, r=0..7. ----
        // reuse stage smem: tpart[NWN][128][8] floats at 0, x_s[128][32] at 32768
        float* tpart = (float*)smem;
        float* x_s = (float*)(smem + NWN * 128 * 8 * 4);
        __syncthreads();
        {
            // load x tile: rows m0..m0+127, d = n0/8 .. +32
            int d0 = n0 / 8;
            int row = tid >> 2, ch = tid & 3;
            float4 v = *reinterpret_cast<const float4*>(
                &xsrc[(size_t)(m0 + row) * Dd + d0 + ch * 8]);
            float4 v2 = *reinterpret_cast<const float4*>(
                &xsrc[(size_t)(m0 + row) * Dd + d0 + ch * 8 + 4]);
            *reinterpret_cast<float4*>(&x_s[row * 32 + ch * 8]) = v;
            *reinterpret_cast<float4*>(&x_s[row * 32 + ch * 8 + 4]) = v2;
        }
        __syncthreads();

        int r0 = (lane & 3) * 2;
        #pragma unroll
        for (int mt = 0; mt < 4; mt++) {
            int row_a = warp_m * 64 + mt * 16 + (lane >> 2);
            int row_b = row_a + 8;
            float t00 = 0.f, t01 = 0.f, t10 = 0.f, t11 = 0.f;
            #pragma unroll
            for (int nt = 0; nt < NT; nt++) {
                int dl = warp_n * NT + nt;
                float xa = x_s[row_a * 32 + dl];
                float xb = x_s[row_b * 32 + dl];
                float bx = 0.f, by = 0.f;
                if constexpr (HAS_BIAS) { bx = biasv[nt].x; by = biasv[nt].y; }
                t00 += xa * (acc[mt][nt][0] + bx);
                t01 += xa * (acc[mt][nt][1] + by);
                t10 += xb * (acc[mt][nt][2] + bx);
                t11 += xb * (acc[mt][nt][3] + by);
            }
            // per-warp slice: no write conflicts (each warp_n its own slab)
            if (mt == 0 && lane < 32) {} // no-op keep structure
            tpart[(warp_n * 128 + row_a) * 8 + r0]     = t00;
            tpart[(warp_n * 128 + row_a) * 8 + r0 + 1] = t01;
            tpart[(warp_n * 128 + row_b) * 8 + r0]     = t10;
            tpart[(warp_n * 128 + row_b) * 8 + r0 + 1] = t11;
        }
        __syncthreads();
        // reduce over NWN slabs: 1024 (row,r) pairs, 512 threads -> 2 each
        #pragma unroll
        for (int i = 0; i < 2; i++) {
            int pr = tid + i * NTHR;      // 0..1023
            int row = pr >> 3, r = pr & 7;
            float s = 0.f;
            #pragma unroll
            for (int w = 0; w < NWN; w++)
                s += tpart[(w * 128 + row) * 8 + r];
            g_tp[((size_t)blockIdx.x * Bsz + m0 + row) * Rr + r] = s;
        }
        return;
    }

    // ---- normal / x_b store ----
    float* Cw;
    if constexpr (SK == 1) {
        Cw = C;
    } else {
        Cw = C + (size_t)z * Bsz * N_;
    }
    int nbase = n0;
    int nstride = N_;
    if constexpr (FUSE_T) { nbase = n0 - XBN; nstride = XBN; }
    #pragma unroll
    for (int mt = 0; mt < 4; mt++) {
        int row0 = m0 + warp_m * 64 + mt * 16 + (lane >> 2);
        #pragma unroll
        for (int nt = 0; nt < NT; nt++) {
            int col = nbase + warp_n * WN + nt * 8 + (lane & 3) * 2;
            float bx = 0.f, by = 0.f;
            if constexpr (HAS_BIAS) { bx = biasv[nt].x; by = biasv[nt].y; }
            float2 v0 = make_float2(acc[mt][nt][0] + bx, acc[mt][nt][1] + by);
            float2 v1 = make_float2(acc[mt][nt][2] + bx, acc[mt][nt][3] + by);
            *reinterpret_cast<float2*>(&Cw[(size_t)row0 * nstride + col]) = v0;
            *reinterpret_cast<float2*>(&Cw[(size_t)(row0 + 8) * nstride + col]) = v1;
        }
    }
}

// ---------------------------------------------------------------------------
// reduce1: h = GELU(sum_z p1[z] + b1) -> bf16 hi/lo
// ---------------------------------------------------------------------------
__global__ void __launch_bounds__(256) reduce1_kernel(const float* __restrict__ b1)
{
    int e = (blockIdx.x * 256 + threadIdx.x) * 4;
    float4 s = *reinterpret_cast<const float4*>(&g_p1[e]);
    #pragma unroll
    for (int z = 1; z < 4; z++) {
        float4 p = *reinterpret_cast<const float4*>(&g_p1[z * (Bsz * Dd) + e]);
        s.x += p.x; s.y += p.y; s.z += p.z; s.w += p.w;
    }
    float4 bb = *reinterpret_cast<const float4*>(&b1[e & (Dd - 1)]);
    float u[4] = {s.x + bb.x, s.y + bb.y, s.z + bb.z, s.w + bb.w};
    __nv_bfloat16 hi[4], lo[4];
    #pragma unroll
    for (int i = 0; i < 4; i++) {
        float g = 0.5f * u[i] * (1.f + erff(u[i] * 0.70710678118654752f));
        hi[i] = __float2bfloat16(g);
        lo[i] = __float2bfloat16(g - __bfloat162float(hi[i]));
    }
    *reinterpret_cast<__nv_bfloat162*>(&g_Ahi[e])     = __halves2bfloat162(hi[0], hi[1]);
    *reinterpret_cast<__nv_bfloat162*>(&g_Ahi[e + 2]) = __halves2bfloat162(hi[2], hi[3]);
    *reinterpret_cast<__nv_bfloat162*>(&g_Alo[e])     = __halves2bfloat162(lo[0], lo[1]);
    *reinterpret_cast<__nv_bfloat162*>(&g_Alo[e + 2]) = __halves2bfloat162(lo[2], lo[3]);
}

// ---------------------------------------------------------------------------
// reduce3: out = x + sum_z p3[z] + rank-8 epilogue; t summed from g_tp.
// grid (2, 256), 256 threads.
// ---------------------------------------------------------------------------
__global__ void __launch_bounds__(256) reduce3_kernel(
    const float* __restrict__ x, float* __restrict__ out)
{
    int b = blockIdx.y;
    __shared__ float t_s[Rr];
    // prologue: t[b][r] = sum over 32 partials. tid<256: lane=p, warp=r
    if (threadIdx.x < 256) {
        int p = threadIdx.x & 31, r = threadIdx.x >> 5;
        float v = g_tp[((size_t)p * Bsz + b) * Rr + r];
        #pragma unroll
        for (int o = 16; o; o >>= 1)
            v += __shfl_down_sync(0xFFFFFFFFu, v, o);
        if (p == 0) t_s[r] = v;
    }
    __syncthreads();

    int o = blockIdx.x * 512 + threadIdx.x * 2;
    size_t e = (size_t)b * Dd + o;
    float2 s = *reinterpret_cast<const float2*>(&x[e]);
    #pragma unroll
    for (int z = 0; z < 4; z++) {
        float2 p = *reinterpret_cast<const float2*>(&g_p3[z * (Bsz * Dd) + e]);
        s.x += p.x; s.y += p.y;
    }
    float t0 = t_s[0], t1 = t_s[1], t2 = t_s[2], t3 = t_s[3];
    float t4 = t_s[4], t5 = t_s[5], t6 = t_s[6], t7 = t_s[7];
    const float* wb = &g_w[(size_t)b * XBN + (size_t)o * Rr];
    float4 w0 = *reinterpret_cast<const float4*>(wb);
    float4 w1 = *reinterpret_cast<const float4*>(wb + 4);
    float4 w2 = *reinterpret_cast<const float4*>(wb + 8);
    float4 w3 = *reinterpret_cast<const float4*>(wb + 12);
    float lr0 = t0*w0.x + t1*w0.y + t2*w0.z + t3*w0.w
              + t4*w1.x + t5*w1.y + t6*w1.z + t7*w1.w;
    float lr1 = t0*w2.x + t1*w2.y + t2*w2.z + t3*w2.w
              + t4*w3.x + t5*w3.y + t6*w3.z + t7*w3.w;
    *reinterpret_cast<float2*>(&out[e]) = make_float2(s.x + lr0, s.y + lr1);
}

// ---------------------------------------------------------------------------
extern "C" void kernel_launch(void* const* d_in, const int* in_sizes, int n_in,
                              void* d_out, int out_size)
{
    const float* x    = (const float*)d_in[0];
    const float* ada  = (const float*)d_in[1];
    const float* base = (const float*)d_in[2];
    const float* gam  = (const float*)d_in[3];
    const float* bet  = (const float*)d_in[4];
    const float* W1   = (const float*)d_in[5];
    const float* b1   = (const float*)d_in[6];
    const float* W2   = (const float*)d_in[7];
    const float* b2   = (const float*)d_in[8];
    float* out = (float*)d_out;

    constexpr int SMEM64  = 3 * (20480 + 128 * 64)  + 2 * (2 * 32 * 72 * 2);   // 104448
    constexpr int SMEM256 = 3 * (20480 + 128 * 256) + 2 * (2 * 32 * 264 * 2);  // 227328

    float *w_p, *p1_p, *p3_p;
    __nv_bfloat16 *chi_p, *clo_p, *ahi_p, *alo_p, *xhi_p, *xlo_p;
    cudaGetSymbolAddress((void**)&w_p,  g_w);
    cudaGetSymbolAddress((void**)&p1_p, g_p1);
    cudaGetSymbolAddress((void**)&p3_p, g_p3);
    cudaGetSymbolAddress((void**)&chi_p, g_Chi);
    cudaGetSymbolAddress((void**)&clo_p, g_Clo);
    cudaGetSymbolAddress((void**)&ahi_p, g_Ahi);
    cudaGetSymbolAddress((void**)&alo_p, g_Alo);
    cudaGetSymbolAddress((void**)&xhi_p, g_Xhi);
    cudaGetSymbolAddress((void**)&xlo_p, g_Xlo);

    auto k13 = gemm_mma_kernel<64, 4, false, 1024, 2, 4, true, 2, false>;
    auto k2  = gemm_mma_kernel<256, 1, true, 16384, 2, 8, false, 1, true>;

    cudaFuncSetAttribute((const void*)k13,
                         cudaFuncAttributeMaxDynamicSharedMemorySize, SMEM64);
    cudaFuncSetAttribute((const void*)k2,
                         cudaFuncAttributeMaxDynamicSharedMemorySize, SMEM256);

    // prepass: LN (256 blocks) + x split (512 blocks)
    prepass_kernel<<<768, 256>>>(ada, gam, bet, x);

    // GEMM1 + GEMM3 fused: z<4 -> cond@W1 partials, z>=4 -> x@base partials
    k13<<<dim3(16, 2, 8), 256, SMEM64>>>(
        chi_p, clo_p, W1, p1_p,
        xhi_p, xlo_p, base, p3_p, nullptr, nullptr);

    // reduce1: + b1, GELU, split -> g_Ahi/g_Alo
    reduce1_kernel<<<(Bsz * Dd) / 1024, 256>>>(b1);

    // GEMM2: single wave, x_a half -> fused t partials, x_b half -> g_w
    k2<<<dim3(W2N / 256, Bsz / BM, 1), 512, SMEM256>>>(
        ahi_p, alo_p, W2, w_p,
        nullptr, nullptr, nullptr, nullptr, b2, x);

    // final epilogue (t reduced in-kernel)
    reduce3_kernel<<<dim3(2, Bsz), 256>>>(x, out);
}